// round 5
// baseline (speedup 1.0000x reference)
#include <cuda_runtime.h>
#include <cuda_bf16.h>
#include <math.h>

#define D_MODEL 1024
#define N_HEADS 16
#define HEAD_DIM 64
#define KV_DIM 256
#define SEQ_T 2048
#define BATCH 2
#define ROWS (BATCH * SEQ_T)   // 4096

typedef unsigned long long ull;

// ---------------- f32x2 packed helpers (sm_103a) ----------------------------
__device__ __forceinline__ void fma2(ull& d, ull a, ull b) {
    asm("fma.rn.f32x2 %0, %1, %2, %0;" : "+l"(d) : "l"(a), "l"(b));
}
__device__ __forceinline__ void mul2(ull& d, ull a) {
    asm("mul.rn.f32x2 %0, %0, %1;" : "+l"(d) : "l"(a));
}
__device__ __forceinline__ ull pk2(float lo, float hi) {
    ull r; asm("mov.b64 %0, {%1, %2};" : "=l"(r) : "f"(lo), "f"(hi)); return r;
}
__device__ __forceinline__ void upk2(ull v, float& lo, float& hi) {
    asm("mov.b64 {%0, %1}, %2;" : "=f"(lo), "=f"(hi) : "l"(v));
}

// ---------------- scratch (device globals; no allocation allowed) -----------
__device__ float g_kv[ROWS * KV_DIM];     // 4 MB
__device__ float g_q [ROWS * D_MODEL];    // 16 MB
__device__ float g_k [ROWS * D_MODEL];    // 16 MB
__device__ float g_v [ROWS * D_MODEL];    // 16 MB
__device__ float g_y [ROWS * D_MODEL];    // 16 MB

// ---------------- SGEMM (f32x2): C = A[MxK] @ B[KxN] + bias -----------------
// 128x128 block, 8x8 microtile as 8x(4 pairs). A tile stored duplicated.
__global__ __launch_bounds__(256, 2) void sgemm_bias2(
    const float* __restrict__ A, const float* __restrict__ B,
    const float* __restrict__ bias, float* __restrict__ C,
    int M, int N, int K)
{
    __shared__ __align__(16) float As2[8][256];   // dup'd, transposed
    __shared__ __align__(16) float Bs[8][128];
    const int tid = threadIdx.x;
    const int bm = blockIdx.y * 128;
    const int bn = blockIdx.x * 128;

    const int a_row = tid >> 1;          // 0..127
    const int a_col = (tid & 1) * 4;     // 0 or 4
    const int b_row = tid >> 5;          // 0..7
    const int b_col = (tid & 31) * 4;    // 0..124
    const int tr = tid >> 4;             // 0..15
    const int tc = tid & 15;             // 0..15

    ull acc[8][4];
    #pragma unroll
    for (int i = 0; i < 8; i++)
        #pragma unroll
        for (int p = 0; p < 4; p++) acc[i][p] = 0ull;

    const float* Aptr = A + (size_t)(bm + a_row) * K + a_col;
    const float* Bptr = B + (size_t)b_row * N + bn + b_col;

    for (int k0 = 0; k0 < K; k0 += 8) {
        float4 av = *(const float4*)(Aptr + k0);
        float4 bv = *(const float4*)(Bptr + (size_t)k0 * N);
        *(float2*)&As2[a_col + 0][2 * a_row] = make_float2(av.x, av.x);
        *(float2*)&As2[a_col + 1][2 * a_row] = make_float2(av.y, av.y);
        *(float2*)&As2[a_col + 2][2 * a_row] = make_float2(av.z, av.z);
        *(float2*)&As2[a_col + 3][2 * a_row] = make_float2(av.w, av.w);
        *(float4*)&Bs[b_row][b_col] = bv;
        __syncthreads();
        #pragma unroll
        for (int k = 0; k < 8; k++) {
            ulonglong2 a01 = *(const ulonglong2*)&As2[k][tr * 16 + 0];
            ulonglong2 a23 = *(const ulonglong2*)&As2[k][tr * 16 + 4];
            ulonglong2 a45 = *(const ulonglong2*)&As2[k][tr * 16 + 8];
            ulonglong2 a67 = *(const ulonglong2*)&As2[k][tr * 16 + 12];
            ulonglong2 b0  = *(const ulonglong2*)&Bs[k][tc * 8 + 0];
            ulonglong2 b1  = *(const ulonglong2*)&Bs[k][tc * 8 + 4];
            fma2(acc[0][0], a01.x, b0.x); fma2(acc[0][1], a01.x, b0.y);
            fma2(acc[0][2], a01.x, b1.x); fma2(acc[0][3], a01.x, b1.y);
            fma2(acc[1][0], a01.y, b0.x); fma2(acc[1][1], a01.y, b0.y);
            fma2(acc[1][2], a01.y, b1.x); fma2(acc[1][3], a01.y, b1.y);
            fma2(acc[2][0], a23.x, b0.x); fma2(acc[2][1], a23.x, b0.y);
            fma2(acc[2][2], a23.x, b1.x); fma2(acc[2][3], a23.x, b1.y);
            fma2(acc[3][0], a23.y, b0.x); fma2(acc[3][1], a23.y, b0.y);
            fma2(acc[3][2], a23.y, b1.x); fma2(acc[3][3], a23.y, b1.y);
            fma2(acc[4][0], a45.x, b0.x); fma2(acc[4][1], a45.x, b0.y);
            fma2(acc[4][2], a45.x, b1.x); fma2(acc[4][3], a45.x, b1.y);
            fma2(acc[5][0], a45.y, b0.x); fma2(acc[5][1], a45.y, b0.y);
            fma2(acc[5][2], a45.y, b1.x); fma2(acc[5][3], a45.y, b1.y);
            fma2(acc[6][0], a67.x, b0.x); fma2(acc[6][1], a67.x, b0.y);
            fma2(acc[6][2], a67.x, b1.x); fma2(acc[6][3], a67.x, b1.y);
            fma2(acc[7][0], a67.y, b0.x); fma2(acc[7][1], a67.y, b0.y);
            fma2(acc[7][2], a67.y, b1.x); fma2(acc[7][3], a67.y, b1.y);
        }
        __syncthreads();
    }

    float4 bias0 = *(const float4*)(bias + bn + tc * 8 + 0);
    float4 bias1 = *(const float4*)(bias + bn + tc * 8 + 4);
    #pragma unroll
    for (int i = 0; i < 8; i++) {
        int row = bm + tr * 8 + i;
        float o[8];
        #pragma unroll
        for (int p = 0; p < 4; p++) upk2(acc[i][p], o[2 * p], o[2 * p + 1]);
        float4 s0 = make_float4(o[0] + bias0.x, o[1] + bias0.y, o[2] + bias0.z, o[3] + bias0.w);
        float4 s1 = make_float4(o[4] + bias1.x, o[5] + bias1.y, o[6] + bias1.z, o[7] + bias1.w);
        *(float4*)&C[(size_t)row * N + bn + tc * 8 + 0] = s0;
        *(float4*)&C[(size_t)row * N + bn + tc * 8 + 4] = s1;
    }
}

// ---------------- RoPE on q (in-place). Layout [ROWS, H*64] -----------------
__global__ void rope_q_kernel(float* __restrict__ q)
{
    int idx = blockIdx.x * blockDim.x + threadIdx.x;   // ROWS*16*32 threads
    if (idx >= ROWS * N_HEADS * 32) return;
    int d   = idx & 31;
    int h   = (idx >> 5) & 15;
    int row = idx >> 9;
    int t   = row & (SEQ_T - 1);
    float inv = powf(10000.0f, -(float)d / 32.0f);
    float ang = (float)t * inv;
    float s, c;
    sincosf(ang, &s, &c);
    float* p = q + (size_t)row * D_MODEL + h * HEAD_DIM + d;
    float q1 = p[0], q2 = p[32];
    p[0]  = q1 * c - q2 * s;
    p[32] = q2 * c + q1 * s;
}

// ------------- k' = (k * t) @ Wkr per (row, head). In-place. ----------------
#define KT_PAIRS 16
__global__ __launch_bounds__(256) void k_transform_kernel(
    float* __restrict__ k, const float* __restrict__ Wkr)
{
    __shared__ float w[64 * 64];
    __shared__ float kin[KT_PAIRS][64];
    const int tid = threadIdx.x;
    const int pair0 = blockIdx.x * KT_PAIRS;    // pair = row*16 + h

    for (int i = tid; i < 4096; i += 256) w[i] = Wkr[i];
    for (int i = tid; i < KT_PAIRS * 64; i += 256) {
        int p   = pair0 + (i >> 6);
        int row = p >> 4, h = p & 15;
        float tpos = (float)(row & (SEQ_T - 1));
        kin[i >> 6][i & 63] = k[(size_t)row * D_MODEL + h * HEAD_DIM + (i & 63)] * tpos;
    }
    __syncthreads();

    const int o0 = tid * 4;
    const int p  = o0 >> 6;
    const int j0 = o0 & 63;
    float out[4] = {0.f, 0.f, 0.f, 0.f};
    #pragma unroll 8
    for (int i = 0; i < 64; i++) {
        float kv_ = kin[p][i];
        #pragma unroll
        for (int c = 0; c < 4; c++) out[c] += kv_ * w[i * 64 + j0 + c];
    }
    int gp = pair0 + p;
    int row = gp >> 4, h = gp & 15;
    #pragma unroll
    for (int c = 0; c < 4; c++)
        k[(size_t)row * D_MODEL + h * HEAD_DIM + j0 + c] = out[c];
}

// ---------------- flash attention (f32x2), causal, 64x64 tiles --------------
// 256 threads: ty=tid>>3 (0..31) -> 2 q rows; tx=tid&7 -> 8 k cols.
// Qs2: [64 d][128] (q duplicated), Ks: [64 d][68], Vs: [64 s][68],
// Ps2: [64 q][132] (s duplicated).
#define QS2_STRIDE 128
#define KS_STRIDE  68
#define VS_STRIDE  68
#define PS2_STRIDE 132

__global__ __launch_bounds__(256, 2) void flash_attn2(
    const float* __restrict__ q, const float* __restrict__ k,
    const float* __restrict__ v, float* __restrict__ y)
{
    extern __shared__ float sm[];
    float* Qs2 = sm;                            // 64*128 = 8192
    float* Ks  = Qs2 + 64 * QS2_STRIDE;         // 64*68  = 4352
    float* Vs  = Ks  + 64 * KS_STRIDE;          // 64*68  = 4352
    float* Ps2 = Vs  + 64 * VS_STRIDE;          // 64*132 = 8448

    const int tid = threadIdx.x;
    const int tx = tid & 7;
    const int ty = tid >> 3;
    const int it = gridDim.x - 1 - blockIdx.x;   // big blocks first
    const int h  = blockIdx.y;
    const int b  = blockIdx.z;
    const int qbase = it * 64;

    // stage Q (scaled by 1/sqrt(64)=0.125), transposed + duplicated
    {
        const float* qp = q + (size_t)(b * SEQ_T + qbase) * D_MODEL + h * HEAD_DIM;
        int qq = tid & 63;
        int dbase = (tid >> 6) * 4;
        #pragma unroll
        for (int rep = 0; rep < 4; rep++) {
            int d4 = dbase + rep * 16;
            float4 vq = *(const float4*)(qp + (size_t)qq * D_MODEL + d4);
            vq.x *= 0.125f; vq.y *= 0.125f; vq.z *= 0.125f; vq.w *= 0.125f;
            *(float2*)&Qs2[(d4 + 0) * QS2_STRIDE + 2 * qq] = make_float2(vq.x, vq.x);
            *(float2*)&Qs2[(d4 + 1) * QS2_STRIDE + 2 * qq] = make_float2(vq.y, vq.y);
            *(float2*)&Qs2[(d4 + 2) * QS2_STRIDE + 2 * qq] = make_float2(vq.z, vq.z);
            *(float2*)&Qs2[(d4 + 3) * QS2_STRIDE + 2 * qq] = make_float2(vq.w, vq.w);
        }
    }

    ull O[2][4];
    #pragma unroll
    for (int r = 0; r < 2; r++)
        #pragma unroll
        for (int p = 0; p < 4; p++) O[r][p] = 0ull;
    float m_[2] = {-1e30f, -1e30f};
    float l_[2] = {0.f, 0.f};

    for (int jt = 0; jt <= it; jt++) {
        __syncthreads();   // prev iter PV done; Qs2 staged (first iter)
        {
            const float* kp = k + (size_t)(b * SEQ_T + jt * 64) * D_MODEL + h * HEAD_DIM;
            const float* vp = v + (size_t)(b * SEQ_T + jt * 64) * D_MODEL + h * HEAD_DIM;
            int kk = tid & 63;
            int dbase = (tid >> 6) * 4;
            #pragma unroll
            for (int rep = 0; rep < 4; rep++) {
                int d4 = dbase + rep * 16;
                float4 vk = *(const float4*)(kp + (size_t)kk * D_MODEL + d4);
                Ks[(d4 + 0) * KS_STRIDE + kk] = vk.x;
                Ks[(d4 + 1) * KS_STRIDE + kk] = vk.y;
                Ks[(d4 + 2) * KS_STRIDE + kk] = vk.z;
                Ks[(d4 + 3) * KS_STRIDE + kk] = vk.w;
            }
            #pragma unroll
            for (int rep = 0; rep < 4; rep++) {
                int idx = rep * 1024 + tid * 4;
                int s = idx >> 6, c = idx & 63;
                *(float4*)&Vs[s * VS_STRIDE + c] =
                    *(const float4*)(vp + (size_t)s * D_MODEL + c);
            }
        }
        __syncthreads();

        // S = Q @ K^T (pre-scaled)
        ull S[2][4];
        #pragma unroll
        for (int r = 0; r < 2; r++)
            #pragma unroll
            for (int p = 0; p < 4; p++) S[r][p] = 0ull;
        #pragma unroll 4
        for (int d = 0; d < 64; d++) {
            ulonglong2 a  = *(const ulonglong2*)&Qs2[d * QS2_STRIDE + 4 * ty];
            ulonglong2 b0 = *(const ulonglong2*)&Ks[d * KS_STRIDE + 8 * tx];
            ulonglong2 b1 = *(const ulonglong2*)&Ks[d * KS_STRIDE + 8 * tx + 4];
            fma2(S[0][0], a.x, b0.x); fma2(S[0][1], a.x, b0.y);
            fma2(S[0][2], a.x, b1.x); fma2(S[0][3], a.x, b1.y);
            fma2(S[1][0], a.y, b0.x); fma2(S[1][1], a.y, b0.y);
            fma2(S[1][2], a.y, b1.x); fma2(S[1][3], a.y, b1.y);
        }

        // softmax (online), P -> Ps2 duplicated
        const bool diag = (jt == it);
        #pragma unroll
        for (int r = 0; r < 2; r++) {
            float Sf[8];
            #pragma unroll
            for (int p = 0; p < 4; p++) upk2(S[r][p], Sf[2 * p], Sf[2 * p + 1]);
            int qg = 2 * ty + r;
            if (diag) {
                #pragma unroll
                for (int c = 0; c < 8; c++)
                    if (8 * tx + c > qg) Sf[c] = -1e30f;
            }
            float mx = Sf[0];
            #pragma unroll
            for (int c = 1; c < 8; c++) mx = fmaxf(mx, Sf[c]);
            mx = fmaxf(mx, __shfl_xor_sync(0xffffffffu, mx, 1, 8));
            mx = fmaxf(mx, __shfl_xor_sync(0xffffffffu, mx, 2, 8));
            mx = fmaxf(mx, __shfl_xor_sync(0xffffffffu, mx, 4, 8));
            float mnew = fmaxf(m_[r], mx);
            float corr = __expf(m_[r] - mnew);
            m_[r] = mnew;
            float rs = 0.f;
            #pragma unroll
            for (int c = 0; c < 8; c++) {
                Sf[c] = __expf(Sf[c] - mnew);
                rs += Sf[c];
            }
            rs += __shfl_xor_sync(0xffffffffu, rs, 1, 8);
            rs += __shfl_xor_sync(0xffffffffu, rs, 2, 8);
            rs += __shfl_xor_sync(0xffffffffu, rs, 4, 8);
            l_[r] = l_[r] * corr + rs;
            ull cd = pk2(corr, corr);
            #pragma unroll
            for (int p = 0; p < 4; p++) mul2(O[r][p], cd);
            #pragma unroll
            for (int c2 = 0; c2 < 4; c2++) {
                *(float4*)&Ps2[qg * PS2_STRIDE + 16 * tx + 4 * c2] =
                    make_float4(Sf[2 * c2], Sf[2 * c2], Sf[2 * c2 + 1], Sf[2 * c2 + 1]);
            }
        }
        __syncthreads();

        // O += P @ V
        #pragma unroll 2
        for (int s2 = 0; s2 < 32; s2++) {
            ulonglong2 p0  = *(const ulonglong2*)&Ps2[(2 * ty + 0) * PS2_STRIDE + 4 * s2];
            ulonglong2 p1  = *(const ulonglong2*)&Ps2[(2 * ty + 1) * PS2_STRIDE + 4 * s2];
            ulonglong2 v0a = *(const ulonglong2*)&Vs[(2 * s2 + 0) * VS_STRIDE + 8 * tx];
            ulonglong2 v0b = *(const ulonglong2*)&Vs[(2 * s2 + 0) * VS_STRIDE + 8 * tx + 4];
            ulonglong2 v1a = *(const ulonglong2*)&Vs[(2 * s2 + 1) * VS_STRIDE + 8 * tx];
            ulonglong2 v1b = *(const ulonglong2*)&Vs[(2 * s2 + 1) * VS_STRIDE + 8 * tx + 4];
            fma2(O[0][0], p0.x, v0a.x); fma2(O[0][1], p0.x, v0a.y);
            fma2(O[0][2], p0.x, v0b.x); fma2(O[0][3], p0.x, v0b.y);
            fma2(O[0][0], p0.y, v1a.x); fma2(O[0][1], p0.y, v1a.y);
            fma2(O[0][2], p0.y, v1b.x); fma2(O[0][3], p0.y, v1b.y);
            fma2(O[1][0], p1.x, v0a.x); fma2(O[1][1], p1.x, v0a.y);
            fma2(O[1][2], p1.x, v0b.x); fma2(O[1][3], p1.x, v0b.y);
            fma2(O[1][0], p1.y, v1a.x); fma2(O[1][1], p1.y, v1a.y);
            fma2(O[1][2], p1.y, v1b.x); fma2(O[1][3], p1.y, v1b.y);
        }
    }

    float* yp = y + (size_t)(b * SEQ_T + qbase) * D_MODEL + h * HEAD_DIM;
    #pragma unroll
    for (int r = 0; r < 2; r++) {
        float inv = 1.0f / l_[r];
        float o[8];
        #pragma unroll
        for (int p = 0; p < 4; p++) upk2(O[r][p], o[2 * p], o[2 * p + 1]);
        float4 s0 = make_float4(o[0] * inv, o[1] * inv, o[2] * inv, o[3] * inv);
        float4 s1 = make_float4(o[4] * inv, o[5] * inv, o[6] * inv, o[7] * inv);
        *(float4*)(yp + (size_t)(2 * ty + r) * D_MODEL + 8 * tx + 0) = s0;
        *(float4*)(yp + (size_t)(2 * ty + r) * D_MODEL + 8 * tx + 4) = s1;
    }
}

// ---------------------------------------------------------------------------
extern "C" void kernel_launch(void* const* d_in, const int* in_sizes, int n_in,
                              void* d_out, int out_size)
{
    const float* x   = (const float*)d_in[0];
    // d_in[1] = mask (causal, known statically — ignored)
    const float* Wq  = (const float*)d_in[2];
    const float* bq  = (const float*)d_in[3];
    const float* Wkv = (const float*)d_in[4];
    const float* bkv = (const float*)d_in[5];
    const float* Wk  = (const float*)d_in[6];
    const float* bk  = (const float*)d_in[7];
    const float* Wv  = (const float*)d_in[8];
    const float* bv  = (const float*)d_in[9];
    const float* Wo  = (const float*)d_in[10];
    const float* bo  = (const float*)d_in[11];
    const float* Wkr = (const float*)d_in[12];
    float* out = (float*)d_out;

    float *kv, *q, *k, *v, *y;
    cudaGetSymbolAddress((void**)&kv, g_kv);
    cudaGetSymbolAddress((void**)&q,  g_q);
    cudaGetSymbolAddress((void**)&k,  g_k);
    cudaGetSymbolAddress((void**)&v,  g_v);
    cudaGetSymbolAddress((void**)&y,  g_y);

    const int fa_smem = (64 * QS2_STRIDE + 64 * KS_STRIDE + 64 * VS_STRIDE +
                         64 * PS2_STRIDE) * (int)sizeof(float);   // 101376
    cudaFuncSetAttribute(flash_attn2,
                         cudaFuncAttributeMaxDynamicSharedMemorySize, fa_smem);

    // kv = x @ Wkv + bkv
    sgemm_bias2<<<dim3(KV_DIM / 128, ROWS / 128), 256>>>(x, Wkv, bkv, kv, ROWS, KV_DIM, D_MODEL);
    // q = x @ Wq + bq
    sgemm_bias2<<<dim3(D_MODEL / 128, ROWS / 128), 256>>>(x, Wq, bq, q, ROWS, D_MODEL, D_MODEL);
    // k = kv @ Wk + bk ; v = kv @ Wv + bv
    sgemm_bias2<<<dim3(D_MODEL / 128, ROWS / 128), 256>>>(kv, Wk, bk, k, ROWS, D_MODEL, KV_DIM);
    sgemm_bias2<<<dim3(D_MODEL / 128, ROWS / 128), 256>>>(kv, Wv, bv, v, ROWS, D_MODEL, KV_DIM);
    // RoPE(q)
    rope_q_kernel<<<(ROWS * N_HEADS * 32) / 256, 256>>>(q);
    // k = (k * t) @ Wkr per head
    k_transform_kernel<<<(ROWS * N_HEADS) / KT_PAIRS, 256>>>(k, Wkr);
    // y = softmax(q k^T / 8, causal) @ v
    flash_attn2<<<dim3(SEQ_T / 64, N_HEADS, BATCH), 256, fa_smem>>>(q, k, v, y);
    // out = y @ Wo + bo
    sgemm_bias2<<<dim3(D_MODEL / 128, ROWS / 128), 256>>>(y, Wo, bo, out, ROWS, D_MODEL, D_MODEL);
}

// round 8
// speedup vs baseline: 2.2742x; 2.2742x over previous
#include <cuda_runtime.h>
#include <cuda_bf16.h>
#include <math.h>
#include <cstdint>

#define D_MODEL 1024
#define N_HEADS 16
#define HEAD_DIM 64
#define KV_DIM 256
#define SEQ_T 2048
#define BATCH 2
#define ROWS (BATCH * SEQ_T)   // 4096

// ===================== scratch (device globals) =============================
__device__ float g_kv[ROWS * KV_DIM];
__device__ float g_q [ROWS * D_MODEL];
__device__ float g_k [ROWS * D_MODEL];
__device__ float g_v [ROWS * D_MODEL];
__device__ float g_y [ROWS * D_MODEL];

__device__ __align__(16) __nv_bfloat16 g_xh [ROWS * D_MODEL];
__device__ __align__(16) __nv_bfloat16 g_xl [ROWS * D_MODEL];
__device__ __align__(16) __nv_bfloat16 g_kvh[ROWS * KV_DIM];
__device__ __align__(16) __nv_bfloat16 g_kvl[ROWS * KV_DIM];
__device__ __align__(16) __nv_bfloat16 g_yh [ROWS * D_MODEL];
__device__ __align__(16) __nv_bfloat16 g_yl [ROWS * D_MODEL];
// transposed weights [N][K], bf16 hi/lo
__device__ __align__(16) __nv_bfloat16 g_Wqh [D_MODEL * D_MODEL];
__device__ __align__(16) __nv_bfloat16 g_Wql [D_MODEL * D_MODEL];
__device__ __align__(16) __nv_bfloat16 g_Wkvh[KV_DIM * D_MODEL];
__device__ __align__(16) __nv_bfloat16 g_Wkvl[KV_DIM * D_MODEL];
__device__ __align__(16) __nv_bfloat16 g_Wkh [D_MODEL * KV_DIM];
__device__ __align__(16) __nv_bfloat16 g_Wkl [D_MODEL * KV_DIM];
__device__ __align__(16) __nv_bfloat16 g_Wvh [D_MODEL * KV_DIM];
__device__ __align__(16) __nv_bfloat16 g_Wvl [D_MODEL * KV_DIM];
__device__ __align__(16) __nv_bfloat16 g_Woh [D_MODEL * D_MODEL];
__device__ __align__(16) __nv_bfloat16 g_Wol [D_MODEL * D_MODEL];

// ===================== conversion kernels ===================================
__global__ void fsplit(const float* __restrict__ X,
                       __nv_bfloat16* __restrict__ H, __nv_bfloat16* __restrict__ L,
                       int n)
{
    int i = blockIdx.x * blockDim.x + threadIdx.x;
    if (i >= n) return;
    float v = X[i];
    __nv_bfloat16 h = __float2bfloat16(v);
    __nv_bfloat16 l = __float2bfloat16(v - __bfloat162float(h));
    H[i] = h; L[i] = l;
}

// W[K][N] fp32 -> Th/Tl[N][K] bf16 (transpose + split)
__global__ __launch_bounds__(256) void wsplit_t(
    const float* __restrict__ W,
    __nv_bfloat16* __restrict__ Th, __nv_bfloat16* __restrict__ Tl,
    int K, int N)
{
    __shared__ float t[32][33];
    const int n0 = blockIdx.x * 32, k0 = blockIdx.y * 32;
    const int tx = threadIdx.x & 31, ty = threadIdx.x >> 5;
    #pragma unroll
    for (int i = 0; i < 4; i++)
        t[ty + i * 8][tx] = W[(size_t)(k0 + ty + i * 8) * N + n0 + tx];
    __syncthreads();
    #pragma unroll
    for (int i = 0; i < 4; i++) {
        float v = t[tx][ty + i * 8];
        __nv_bfloat16 h = __float2bfloat16(v);
        __nv_bfloat16 l = __float2bfloat16(v - __bfloat162float(h));
        size_t o = (size_t)(n0 + ty + i * 8) * K + k0 + tx;
        Th[o] = h; Tl[o] = l;
    }
}

// ===================== mma.sync GEMM (legacy tensor path) ===================
// C[M x N] = (Ah+Al)[MxK] @ (Bh+Bl)^T ([N][K]) + bias, 3 bf16 passes in fp32 acc.
// CTA 128x128, 8 warps (2x4 -> 64x32 each), K-chunk 64, cp.async double buffer.
#define LDS_ 72                       // padded row stride in bf16 elements (144B)
#define STAGE_BYTES (2 * 9216 * 2)    // A(128x72) + B(128x72) bf16 = 36864
#define GEMM_SMEM (2 * STAGE_BYTES)   // 73728

__device__ __forceinline__ uint32_t smem_u32(const void* p) {
    uint32_t a;
    asm("{ .reg .u64 t; cvta.to.shared.u64 t, %1; cvt.u32.u64 %0, t; }"
        : "=r"(a) : "l"(p));
    return a;
}

__device__ __forceinline__ void ldmx4(uint32_t addr, uint32_t& r0, uint32_t& r1,
                                      uint32_t& r2, uint32_t& r3)
{
    asm volatile("ldmatrix.sync.aligned.m8n8.x4.shared.b16 {%0,%1,%2,%3}, [%4];"
        : "=r"(r0), "=r"(r1), "=r"(r2), "=r"(r3) : "r"(addr));
}

__device__ __forceinline__ void mma16816(float* d, const uint32_t* a, const uint32_t* b)
{
    asm volatile(
        "mma.sync.aligned.m16n8k16.row.col.f32.bf16.bf16.f32 "
        "{%0,%1,%2,%3}, {%4,%5,%6,%7}, {%8,%9}, {%0,%1,%2,%3};"
        : "+f"(d[0]), "+f"(d[1]), "+f"(d[2]), "+f"(d[3])
        : "r"(a[0]), "r"(a[1]), "r"(a[2]), "r"(a[3]), "r"(b[0]), "r"(b[1]));
}

__global__ __launch_bounds__(256) void gemm_mma(
    const __nv_bfloat16* __restrict__ Ah, const __nv_bfloat16* __restrict__ Al,
    const __nv_bfloat16* __restrict__ Bh, const __nv_bfloat16* __restrict__ Bl,
    const float* __restrict__ bias, float* __restrict__ C, int K, int N)
{
    extern __shared__ __align__(16) char smem[];
    const uint32_t sbase = smem_u32(smem);
    const int tid = threadIdx.x;
    const int lid = tid & 31;
    const int wid = tid >> 5;
    const int wm = wid >> 2;             // 0..1  (64 rows)
    const int wn = wid & 3;              // 0..3  (32 cols)
    const int bm = blockIdx.y * 128;
    const int bn = blockIdx.x * 128;

    float acc[4][4][4];
    #pragma unroll
    for (int mi = 0; mi < 4; mi++)
        #pragma unroll
        for (int ni = 0; ni < 4; ni++)
            #pragma unroll
            for (int e = 0; e < 4; e++) acc[mi][ni][e] = 0.f;

    const int nkc = K >> 6;              // chunks of 64
    const int total = 3 * nkc;

    // issue cp.async loads for chunk cc into stage s
    auto issue = [&](int cc, int s) {
        int p  = cc / nkc;
        int kc = cc - p * nkc;
        const __nv_bfloat16* Ap = ((p == 1) ? Al : Ah) + (size_t)bm * K + kc * 64;
        const __nv_bfloat16* Bp = ((p == 2) ? Bl : Bh) + (size_t)bn * K + kc * 64;
        uint32_t sa = sbase + s * STAGE_BYTES;
        uint32_t sb = sa + 9216 * 2;
        #pragma unroll
        for (int i = 0; i < 4; i++) {
            int c = tid + i * 256;
            int r = c >> 3, e = (c & 7) * 8;
            asm volatile("cp.async.cg.shared.global [%0], [%1], 16;"
                :: "r"(sa + (uint32_t)(r * LDS_ + e) * 2), "l"(Ap + (size_t)r * K + e));
        }
        #pragma unroll
        for (int i = 0; i < 4; i++) {
            int c = tid + i * 256;
            int r = c >> 3, e = (c & 7) * 8;
            asm volatile("cp.async.cg.shared.global [%0], [%1], 16;"
                :: "r"(sb + (uint32_t)(r * LDS_ + e) * 2), "l"(Bp + (size_t)r * K + e));
        }
        asm volatile("cp.async.commit_group;");
    };

    issue(0, 0);

    for (int cc = 0; cc < total; cc++) {
        if (cc + 1 < total) {
            issue(cc + 1, (cc + 1) & 1);
            asm volatile("cp.async.wait_group 1;");
        } else {
            asm volatile("cp.async.wait_group 0;");
        }
        __syncthreads();

        uint32_t sa = sbase + (cc & 1) * STAGE_BYTES;
        uint32_t sb = sa + 9216 * 2;
        #pragma unroll
        for (int ks = 0; ks < 4; ks++) {
            uint32_t a[4][4];
            #pragma unroll
            for (int mi = 0; mi < 4; mi++) {
                int row = wm * 64 + mi * 16 + (lid & 15);
                int col = ks * 16 + (lid >> 4) * 8;
                ldmx4(sa + (uint32_t)(row * LDS_ + col) * 2,
                      a[mi][0], a[mi][1], a[mi][2], a[mi][3]);
            }
            uint32_t b[4][2];
            #pragma unroll
            for (int np = 0; np < 2; np++) {
                int row = wn * 32 + np * 16 + ((lid >> 4) & 1) * 8 + (lid & 7);
                int col = ks * 16 + ((lid >> 3) & 1) * 8;
                uint32_t r0, r1, r2, r3;
                ldmx4(sb + (uint32_t)(row * LDS_ + col) * 2, r0, r1, r2, r3);
                b[2 * np][0] = r0; b[2 * np][1] = r1;
                b[2 * np + 1][0] = r2; b[2 * np + 1][1] = r3;
            }
            #pragma unroll
            for (int mi = 0; mi < 4; mi++)
                #pragma unroll
                for (int ni = 0; ni < 4; ni++)
                    mma16816(acc[mi][ni], a[mi], b[ni]);
        }
        __syncthreads();
    }

    // epilogue: fragment -> gmem with bias, float2 stores
    const int gr = lid >> 2;            // 0..7
    const int gc = (lid & 3) * 2;       // 0,2,4,6
    #pragma unroll
    for (int mi = 0; mi < 4; mi++) {
        #pragma unroll
        for (int ni = 0; ni < 4; ni++) {
            int row0 = bm + wm * 64 + mi * 16 + gr;
            int col0 = bn + wn * 32 + ni * 8 + gc;
            float2 b01 = *(const float2*)(bias + col0);
            float2 v0 = make_float2(acc[mi][ni][0] + b01.x, acc[mi][ni][1] + b01.y);
            float2 v1 = make_float2(acc[mi][ni][2] + b01.x, acc[mi][ni][3] + b01.y);
            *(float2*)(C + (size_t)row0 * N + col0) = v0;
            *(float2*)(C + (size_t)(row0 + 8) * N + col0) = v1;
        }
    }
}

// ===================== RoPE on q (R3) =======================================
__global__ void rope_q_kernel(float* __restrict__ q)
{
    int idx = blockIdx.x * blockDim.x + threadIdx.x;
    if (idx >= ROWS * N_HEADS * 32) return;
    int d   = idx & 31;
    int h   = (idx >> 5) & 15;
    int row = idx >> 9;
    int t   = row & (SEQ_T - 1);
    float inv = powf(10000.0f, -(float)d / 32.0f);
    float ang = (float)t * inv;
    float s, c;
    sincosf(ang, &s, &c);
    float* p = q + (size_t)row * D_MODEL + h * HEAD_DIM + d;
    float q1 = p[0], q2 = p[32];
    p[0]  = q1 * c - q2 * s;
    p[32] = q2 * c + q1 * s;
}

// ========== k' = (k * t) @ Wkr per (row, head). In-place (R3). ==============
#define KT_PAIRS 16
__global__ __launch_bounds__(256) void k_transform_kernel(
    float* __restrict__ k, const float* __restrict__ Wkr)
{
    __shared__ float w[64 * 64];
    __shared__ float kin[KT_PAIRS][64];
    const int tid = threadIdx.x;
    const int pair0 = blockIdx.x * KT_PAIRS;

    for (int i = tid; i < 4096; i += 256) w[i] = Wkr[i];
    for (int i = tid; i < KT_PAIRS * 64; i += 256) {
        int p   = pair0 + (i >> 6);
        int row = p >> 4, h = p & 15;
        float tpos = (float)(row & (SEQ_T - 1));
        kin[i >> 6][i & 63] = k[(size_t)row * D_MODEL + h * HEAD_DIM + (i & 63)] * tpos;
    }
    __syncthreads();

    const int o0 = tid * 4;
    const int p  = o0 >> 6;
    const int j0 = o0 & 63;
    float out[4] = {0.f, 0.f, 0.f, 0.f};
    #pragma unroll 8
    for (int i = 0; i < 64; i++) {
        float kv_ = kin[p][i];
        #pragma unroll
        for (int c = 0; c < 4; c++) out[c] += kv_ * w[i * 64 + j0 + c];
    }
    int gp = pair0 + p;
    int row = gp >> 4, h = gp & 15;
    #pragma unroll
    for (int c = 0; c < 4; c++)
        k[(size_t)row * D_MODEL + h * HEAD_DIM + j0 + c] = out[c];
}

// ============ flash attention (fp32, R3-proven), causal, 64x64 ==============
__global__ __launch_bounds__(256) void flash_attn_kernel(
    const float* __restrict__ q, const float* __restrict__ k,
    const float* __restrict__ v, float* __restrict__ y)
{
    extern __shared__ float sm[];
    float* Qs = sm;
    float* Ks = sm + 4096;
    float* Vs = Ks + 64 * 65;

    const int tid = threadIdx.x;
    const int ty = tid >> 4, tx = tid & 15;
    const int it = blockIdx.x;
    const int h  = blockIdx.y;
    const int b  = blockIdx.z;
    const int qbase = it * 64;

    const float* qp = q + ((size_t)(b * SEQ_T + qbase)) * D_MODEL + h * HEAD_DIM;
    for (int i = tid; i < 4096; i += 256)
        Qs[i] = qp[(size_t)(i >> 6) * D_MODEL + (i & 63)];

    float m_[4], l_[4], O[4][4];
    #pragma unroll
    for (int r = 0; r < 4; r++) {
        m_[r] = -1e30f; l_[r] = 0.f;
        #pragma unroll
        for (int c = 0; c < 4; c++) O[r][c] = 0.f;
    }

    for (int jt = 0; jt <= it; jt++) {
        const int kbase = jt * 64;
        const float* kp = k + ((size_t)(b * SEQ_T + kbase)) * D_MODEL + h * HEAD_DIM;
        const float* vp = v + ((size_t)(b * SEQ_T + kbase)) * D_MODEL + h * HEAD_DIM;
        __syncthreads();
        for (int i = tid; i < 4096; i += 256) {
            int rr = i >> 6, cc = i & 63;
            Ks[rr * 65 + cc] = kp[(size_t)rr * D_MODEL + cc];
            Vs[i]            = vp[(size_t)rr * D_MODEL + cc];
        }
        __syncthreads();

        float S[4][4];
        #pragma unroll
        for (int r = 0; r < 4; r++)
            #pragma unroll
            for (int c = 0; c < 4; c++) S[r][c] = 0.f;
        #pragma unroll 4
        for (int d = 0; d < 64; d++) {
            float ra[4], rb[4];
            #pragma unroll
            for (int r = 0; r < 4; r++) ra[r] = Qs[(ty * 4 + r) * 64 + d];
            #pragma unroll
            for (int c = 0; c < 4; c++) rb[c] = Ks[(tx * 4 + c) * 65 + d];
            #pragma unroll
            for (int r = 0; r < 4; r++)
                #pragma unroll
                for (int c = 0; c < 4; c++) S[r][c] += ra[r] * rb[c];
        }

        const float scale = 0.125f;
        const bool diag = (jt == it);
        float corr[4];
        #pragma unroll
        for (int r = 0; r < 4; r++) {
            #pragma unroll
            for (int c = 0; c < 4; c++) {
                float s_ = S[r][c] * scale;
                if (diag && (tx * 4 + c) > (ty * 4 + r)) s_ = -1e30f;
                S[r][c] = s_;
            }
            float mx = fmaxf(fmaxf(S[r][0], S[r][1]), fmaxf(S[r][2], S[r][3]));
            #pragma unroll
            for (int off = 8; off; off >>= 1)
                mx = fmaxf(mx, __shfl_xor_sync(0xffffffffu, mx, off, 16));
            float mnew = fmaxf(m_[r], mx);
            corr[r] = __expf(m_[r] - mnew);
            m_[r] = mnew;
            float rs = 0.f;
            #pragma unroll
            for (int c = 0; c < 4; c++) {
                float p_ = __expf(S[r][c] - mnew);
                S[r][c] = p_;
                rs += p_;
            }
            #pragma unroll
            for (int off = 8; off; off >>= 1)
                rs += __shfl_xor_sync(0xffffffffu, rs, off, 16);
            l_[r] = l_[r] * corr[r] + rs;
            #pragma unroll
            for (int c = 0; c < 4; c++) O[r][c] *= corr[r];
        }

        __syncthreads();
        #pragma unroll
        for (int r = 0; r < 4; r++)
            #pragma unroll
            for (int c = 0; c < 4; c++)
                Ks[(ty * 4 + r) * 65 + tx * 4 + c] = S[r][c];
        __syncthreads();
        #pragma unroll 4
        for (int s = 0; s < 64; s++) {
            float ra[4];
            #pragma unroll
            for (int r = 0; r < 4; r++) ra[r] = Ks[(ty * 4 + r) * 65 + s];
            float4 bv = *(float4*)&Vs[s * 64 + tx * 4];
            float rb[4] = {bv.x, bv.y, bv.z, bv.w};
            #pragma unroll
            for (int r = 0; r < 4; r++)
                #pragma unroll
                for (int c = 0; c < 4; c++) O[r][c] += ra[r] * rb[c];
        }
    }

    float* yp = y + ((size_t)(b * SEQ_T + qbase)) * D_MODEL + h * HEAD_DIM;
    #pragma unroll
    for (int r = 0; r < 4; r++) {
        float inv = 1.0f / l_[r];
        #pragma unroll
        for (int c = 0; c < 4; c++)
            yp[(size_t)(ty * 4 + r) * D_MODEL + tx * 4 + c] = O[r][c] * inv;
    }
}

// ===================== launch ===============================================
extern "C" void kernel_launch(void* const* d_in, const int* in_sizes, int n_in,
                              void* d_out, int out_size)
{
    const float* x   = (const float*)d_in[0];
    // d_in[1] = mask (causal, static — ignored)
    const float* Wq  = (const float*)d_in[2];
    const float* bq  = (const float*)d_in[3];
    const float* Wkv = (const float*)d_in[4];
    const float* bkv = (const float*)d_in[5];
    const float* Wk  = (const float*)d_in[6];
    const float* bk  = (const float*)d_in[7];
    const float* Wv  = (const float*)d_in[8];
    const float* bv  = (const float*)d_in[9];
    const float* Wo  = (const float*)d_in[10];
    const float* bo  = (const float*)d_in[11];
    const float* Wkr = (const float*)d_in[12];
    float* out = (float*)d_out;

    float *kv, *q, *k, *v, *y;
    cudaGetSymbolAddress((void**)&kv, g_kv);
    cudaGetSymbolAddress((void**)&q,  g_q);
    cudaGetSymbolAddress((void**)&k,  g_k);
    cudaGetSymbolAddress((void**)&v,  g_v);
    cudaGetSymbolAddress((void**)&y,  g_y);
    __nv_bfloat16 *xh, *xl, *kvh, *kvl, *yh, *yl;
    __nv_bfloat16 *Wqh, *Wql, *Wkvh, *Wkvl, *Wkh, *Wkl, *Wvh, *Wvl, *Woh, *Wol;
    cudaGetSymbolAddress((void**)&xh,  g_xh);   cudaGetSymbolAddress((void**)&xl,  g_xl);
    cudaGetSymbolAddress((void**)&kvh, g_kvh);  cudaGetSymbolAddress((void**)&kvl, g_kvl);
    cudaGetSymbolAddress((void**)&yh,  g_yh);   cudaGetSymbolAddress((void**)&yl,  g_yl);
    cudaGetSymbolAddress((void**)&Wqh, g_Wqh);  cudaGetSymbolAddress((void**)&Wql, g_Wql);
    cudaGetSymbolAddress((void**)&Wkvh,g_Wkvh); cudaGetSymbolAddress((void**)&Wkvl,g_Wkvl);
    cudaGetSymbolAddress((void**)&Wkh, g_Wkh);  cudaGetSymbolAddress((void**)&Wkl, g_Wkl);
    cudaGetSymbolAddress((void**)&Wvh, g_Wvh);  cudaGetSymbolAddress((void**)&Wvl, g_Wvl);
    cudaGetSymbolAddress((void**)&Woh, g_Woh);  cudaGetSymbolAddress((void**)&Wol, g_Wol);

    cudaFuncSetAttribute(gemm_mma, cudaFuncAttributeMaxDynamicSharedMemorySize, GEMM_SMEM);
    const int fa_smem = (4096 + 64 * 65 + 4096) * (int)sizeof(float);
    cudaFuncSetAttribute(flash_attn_kernel,
                         cudaFuncAttributeMaxDynamicSharedMemorySize, fa_smem);

    // weight transpose+split:  W[K][N] -> [N][K] hi/lo
    wsplit_t<<<dim3(D_MODEL/32, D_MODEL/32), 256>>>(Wq,  Wqh,  Wql,  D_MODEL, D_MODEL);
    wsplit_t<<<dim3(KV_DIM/32,  D_MODEL/32), 256>>>(Wkv, Wkvh, Wkvl, D_MODEL, KV_DIM);
    wsplit_t<<<dim3(D_MODEL/32, KV_DIM/32),  256>>>(Wk,  Wkh,  Wkl,  KV_DIM,  D_MODEL);
    wsplit_t<<<dim3(D_MODEL/32, KV_DIM/32),  256>>>(Wv,  Wvh,  Wvl,  KV_DIM,  D_MODEL);
    wsplit_t<<<dim3(D_MODEL/32, D_MODEL/32), 256>>>(Wo,  Woh,  Wol,  D_MODEL, D_MODEL);
    // activation split: x
    fsplit<<<(ROWS * D_MODEL) / 256, 256>>>(x, xh, xl, ROWS * D_MODEL);

    // kv = x @ Wkv + bkv   (N = 256)
    gemm_mma<<<dim3(KV_DIM/128, ROWS/128), 256, GEMM_SMEM>>>(xh, xl, Wkvh, Wkvl, bkv, kv, D_MODEL, KV_DIM);
    fsplit<<<(ROWS * KV_DIM) / 256, 256>>>(kv, kvh, kvl, ROWS * KV_DIM);
    // q = x @ Wq + bq
    gemm_mma<<<dim3(D_MODEL/128, ROWS/128), 256, GEMM_SMEM>>>(xh, xl, Wqh, Wql, bq, q, D_MODEL, D_MODEL);
    // k = kv @ Wk + bk ; v = kv @ Wv + bv   (K = 256)
    gemm_mma<<<dim3(D_MODEL/128, ROWS/128), 256, GEMM_SMEM>>>(kvh, kvl, Wkh, Wkl, bk, k, KV_DIM, D_MODEL);
    gemm_mma<<<dim3(D_MODEL/128, ROWS/128), 256, GEMM_SMEM>>>(kvh, kvl, Wvh, Wvl, bv, v, KV_DIM, D_MODEL);
    // RoPE(q); k = (k*t) @ Wkr
    rope_q_kernel<<<(ROWS * N_HEADS * 32) / 256, 256>>>(q);
    k_transform_kernel<<<(ROWS * N_HEADS) / KT_PAIRS, 256>>>(k, Wkr);
    // attention (fp32, proven)
    flash_attn_kernel<<<dim3(SEQ_T / 64, N_HEADS, BATCH), 256, fa_smem>>>(q, k, v, y);
    // out = y @ Wo + bo
    fsplit<<<(ROWS * D_MODEL) / 256, 256>>>(y, yh, yl, ROWS * D_MODEL);
    gemm_mma<<<dim3(D_MODEL/128, ROWS/128), 256, GEMM_SMEM>>>(yh, yl, Woh, Wol, bo, out, D_MODEL, D_MODEL);
}

// round 9
// speedup vs baseline: 3.9360x; 1.7307x over previous
#include <cuda_runtime.h>
#include <cuda_bf16.h>
#include <math.h>
#include <cstdint>

#define D_MODEL 1024
#define N_HEADS 16
#define HEAD_DIM 64
#define KV_DIM 256
#define SEQ_T 2048
#define BATCH 2
#define ROWS (BATCH * SEQ_T)   // 4096

// ===================== scratch (device globals) =============================
__device__ float g_kv[ROWS * KV_DIM];
__device__ float g_q [ROWS * D_MODEL];
__device__ float g_k [ROWS * D_MODEL];
__device__ float g_v [ROWS * D_MODEL];
__device__ float g_y [ROWS * D_MODEL];

__device__ __align__(16) __nv_bfloat16 g_xh [ROWS * D_MODEL];
__device__ __align__(16) __nv_bfloat16 g_xl [ROWS * D_MODEL];
__device__ __align__(16) __nv_bfloat16 g_kvh[ROWS * KV_DIM];
__device__ __align__(16) __nv_bfloat16 g_kvl[ROWS * KV_DIM];
__device__ __align__(16) __nv_bfloat16 g_yh [ROWS * D_MODEL];
__device__ __align__(16) __nv_bfloat16 g_yl [ROWS * D_MODEL];
// attention operand splits
__device__ __align__(16) __nv_bfloat16 g_qh [ROWS * D_MODEL];
__device__ __align__(16) __nv_bfloat16 g_ql [ROWS * D_MODEL];
__device__ __align__(16) __nv_bfloat16 g_kh2[ROWS * D_MODEL];
__device__ __align__(16) __nv_bfloat16 g_kl2[ROWS * D_MODEL];
__device__ __align__(16) __nv_bfloat16 g_vh2[ROWS * D_MODEL];
__device__ __align__(16) __nv_bfloat16 g_vl2[ROWS * D_MODEL];
// transposed weights [N][K], bf16 hi/lo
__device__ __align__(16) __nv_bfloat16 g_Wqh [D_MODEL * D_MODEL];
__device__ __align__(16) __nv_bfloat16 g_Wql [D_MODEL * D_MODEL];
__device__ __align__(16) __nv_bfloat16 g_Wkvh[KV_DIM * D_MODEL];
__device__ __align__(16) __nv_bfloat16 g_Wkvl[KV_DIM * D_MODEL];
__device__ __align__(16) __nv_bfloat16 g_Wkh [D_MODEL * KV_DIM];
__device__ __align__(16) __nv_bfloat16 g_Wkl [D_MODEL * KV_DIM];
__device__ __align__(16) __nv_bfloat16 g_Wvh [D_MODEL * KV_DIM];
__device__ __align__(16) __nv_bfloat16 g_Wvl [D_MODEL * KV_DIM];
__device__ __align__(16) __nv_bfloat16 g_Woh [D_MODEL * D_MODEL];
__device__ __align__(16) __nv_bfloat16 g_Wol [D_MODEL * D_MODEL];

// ===================== small helpers ========================================
__device__ __forceinline__ uint32_t smem_u32(const void* p) {
    uint32_t a;
    asm("{ .reg .u64 t; cvta.to.shared.u64 t, %1; cvt.u32.u64 %0, t; }"
        : "=r"(a) : "l"(p));
    return a;
}
__device__ __forceinline__ float ex2f(float x) {
    float y; asm("ex2.approx.f32 %0, %1;" : "=f"(y) : "f"(x)); return y;
}
// pack (lo, hi) floats -> bf16x2 (lo in low half)
__device__ __forceinline__ uint32_t packbf(float lo, float hi) {
    uint32_t r; asm("cvt.rn.bf16x2.f32 %0, %1, %2;" : "=r"(r) : "f"(hi), "f"(lo));
    return r;
}

__device__ __forceinline__ void ldmx4(uint32_t addr, uint32_t& r0, uint32_t& r1,
                                      uint32_t& r2, uint32_t& r3)
{
    asm volatile("ldmatrix.sync.aligned.m8n8.x4.shared.b16 {%0,%1,%2,%3}, [%4];"
        : "=r"(r0), "=r"(r1), "=r"(r2), "=r"(r3) : "r"(addr));
}
__device__ __forceinline__ void ldmx4t(uint32_t addr, uint32_t& r0, uint32_t& r1,
                                       uint32_t& r2, uint32_t& r3)
{
    asm volatile("ldmatrix.sync.aligned.m8n8.x4.trans.shared.b16 {%0,%1,%2,%3}, [%4];"
        : "=r"(r0), "=r"(r1), "=r"(r2), "=r"(r3) : "r"(addr));
}
__device__ __forceinline__ void mma16816(float* d, const uint32_t* a, const uint32_t* b)
{
    asm volatile(
        "mma.sync.aligned.m16n8k16.row.col.f32.bf16.bf16.f32 "
        "{%0,%1,%2,%3}, {%4,%5,%6,%7}, {%8,%9}, {%0,%1,%2,%3};"
        : "+f"(d[0]), "+f"(d[1]), "+f"(d[2]), "+f"(d[3])
        : "r"(a[0]), "r"(a[1]), "r"(a[2]), "r"(a[3]), "r"(b[0]), "r"(b[1]));
}

// ===================== conversion kernels ===================================
__global__ void fsplit(const float* __restrict__ X,
                       __nv_bfloat16* __restrict__ H, __nv_bfloat16* __restrict__ L,
                       int n)
{
    int i = blockIdx.x * blockDim.x + threadIdx.x;
    if (i >= n) return;
    float v = X[i];
    __nv_bfloat16 h = __float2bfloat16(v);
    __nv_bfloat16 l = __float2bfloat16(v - __bfloat162float(h));
    H[i] = h; L[i] = l;
}

// W[K][N] fp32 -> Th/Tl[N][K] bf16 (transpose + split)
__global__ __launch_bounds__(256) void wsplit_t(
    const float* __restrict__ W,
    __nv_bfloat16* __restrict__ Th, __nv_bfloat16* __restrict__ Tl,
    int K, int N)
{
    __shared__ float t[32][33];
    const int n0 = blockIdx.x * 32, k0 = blockIdx.y * 32;
    const int tx = threadIdx.x & 31, ty = threadIdx.x >> 5;
    #pragma unroll
    for (int i = 0; i < 4; i++)
        t[ty + i * 8][tx] = W[(size_t)(k0 + ty + i * 8) * N + n0 + tx];
    __syncthreads();
    #pragma unroll
    for (int i = 0; i < 4; i++) {
        float v = t[tx][ty + i * 8];
        __nv_bfloat16 h = __float2bfloat16(v);
        __nv_bfloat16 l = __float2bfloat16(v - __bfloat162float(h));
        size_t o = (size_t)(n0 + ty + i * 8) * K + k0 + tx;
        Th[o] = h; Tl[o] = l;
    }
}

// ===================== mma.sync GEMM (R8-proven) ============================
#define LDS_ 72
#define STAGE_BYTES (2 * 9216 * 2)
#define GEMM_SMEM (2 * STAGE_BYTES)

__global__ __launch_bounds__(256) void gemm_mma(
    const __nv_bfloat16* __restrict__ Ah, const __nv_bfloat16* __restrict__ Al,
    const __nv_bfloat16* __restrict__ Bh, const __nv_bfloat16* __restrict__ Bl,
    const float* __restrict__ bias, float* __restrict__ C, int K, int N)
{
    extern __shared__ __align__(16) char smem[];
    const uint32_t sbase = smem_u32(smem);
    const int tid = threadIdx.x;
    const int lid = tid & 31;
    const int wid = tid >> 5;
    const int wm = wid >> 2;
    const int wn = wid & 3;
    const int bm = blockIdx.y * 128;
    const int bn = blockIdx.x * 128;

    float acc[4][4][4];
    #pragma unroll
    for (int mi = 0; mi < 4; mi++)
        #pragma unroll
        for (int ni = 0; ni < 4; ni++)
            #pragma unroll
            for (int e = 0; e < 4; e++) acc[mi][ni][e] = 0.f;

    const int nkc = K >> 6;
    const int total = 3 * nkc;

    auto issue = [&](int cc, int s) {
        int p  = cc / nkc;
        int kc = cc - p * nkc;
        const __nv_bfloat16* Ap = ((p == 1) ? Al : Ah) + (size_t)bm * K + kc * 64;
        const __nv_bfloat16* Bp = ((p == 2) ? Bl : Bh) + (size_t)bn * K + kc * 64;
        uint32_t sa = sbase + s * STAGE_BYTES;
        uint32_t sb = sa + 9216 * 2;
        #pragma unroll
        for (int i = 0; i < 4; i++) {
            int c = tid + i * 256;
            int r = c >> 3, e = (c & 7) * 8;
            asm volatile("cp.async.cg.shared.global [%0], [%1], 16;"
                :: "r"(sa + (uint32_t)(r * LDS_ + e) * 2), "l"(Ap + (size_t)r * K + e));
        }
        #pragma unroll
        for (int i = 0; i < 4; i++) {
            int c = tid + i * 256;
            int r = c >> 3, e = (c & 7) * 8;
            asm volatile("cp.async.cg.shared.global [%0], [%1], 16;"
                :: "r"(sb + (uint32_t)(r * LDS_ + e) * 2), "l"(Bp + (size_t)r * K + e));
        }
        asm volatile("cp.async.commit_group;");
    };

    issue(0, 0);

    for (int cc = 0; cc < total; cc++) {
        if (cc + 1 < total) {
            issue(cc + 1, (cc + 1) & 1);
            asm volatile("cp.async.wait_group 1;");
        } else {
            asm volatile("cp.async.wait_group 0;");
        }
        __syncthreads();

        uint32_t sa = sbase + (cc & 1) * STAGE_BYTES;
        uint32_t sb = sa + 9216 * 2;
        #pragma unroll
        for (int ks = 0; ks < 4; ks++) {
            uint32_t a[4][4];
            #pragma unroll
            for (int mi = 0; mi < 4; mi++) {
                int row = wm * 64 + mi * 16 + (lid & 15);
                int col = ks * 16 + (lid >> 4) * 8;
                ldmx4(sa + (uint32_t)(row * LDS_ + col) * 2,
                      a[mi][0], a[mi][1], a[mi][2], a[mi][3]);
            }
            uint32_t b[4][2];
            #pragma unroll
            for (int np = 0; np < 2; np++) {
                int row = wn * 32 + np * 16 + ((lid >> 4) & 1) * 8 + (lid & 7);
                int col = ks * 16 + ((lid >> 3) & 1) * 8;
                uint32_t r0, r1, r2, r3;
                ldmx4(sb + (uint32_t)(row * LDS_ + col) * 2, r0, r1, r2, r3);
                b[2 * np][0] = r0; b[2 * np][1] = r1;
                b[2 * np + 1][0] = r2; b[2 * np + 1][1] = r3;
            }
            #pragma unroll
            for (int mi = 0; mi < 4; mi++)
                #pragma unroll
                for (int ni = 0; ni < 4; ni++)
                    mma16816(acc[mi][ni], a[mi], b[ni]);
        }
        __syncthreads();
    }

    const int gr = lid >> 2;
    const int gc = (lid & 3) * 2;
    #pragma unroll
    for (int mi = 0; mi < 4; mi++) {
        #pragma unroll
        for (int ni = 0; ni < 4; ni++) {
            int row0 = bm + wm * 64 + mi * 16 + gr;
            int col0 = bn + wn * 32 + ni * 8 + gc;
            float2 b01 = *(const float2*)(bias + col0);
            float2 v0 = make_float2(acc[mi][ni][0] + b01.x, acc[mi][ni][1] + b01.y);
            float2 v1 = make_float2(acc[mi][ni][2] + b01.x, acc[mi][ni][3] + b01.y);
            *(float2*)(C + (size_t)row0 * N + col0) = v0;
            *(float2*)(C + (size_t)(row0 + 8) * N + col0) = v1;
        }
    }
}

// ===================== RoPE on q ============================================
__global__ void rope_q_kernel(float* __restrict__ q)
{
    int idx = blockIdx.x * blockDim.x + threadIdx.x;
    if (idx >= ROWS * N_HEADS * 32) return;
    int d   = idx & 31;
    int h   = (idx >> 5) & 15;
    int row = idx >> 9;
    int t   = row & (SEQ_T - 1);
    float inv = powf(10000.0f, -(float)d / 32.0f);
    float ang = (float)t * inv;
    float s, c;
    sincosf(ang, &s, &c);
    float* p = q + (size_t)row * D_MODEL + h * HEAD_DIM + d;
    float q1 = p[0], q2 = p[32];
    p[0]  = q1 * c - q2 * s;
    p[32] = q2 * c + q1 * s;
}

// ========== k' = (k * t) @ Wkr per (row, head). In-place. ===================
#define KT_PAIRS 16
__global__ __launch_bounds__(256) void k_transform_kernel(
    float* __restrict__ k, const float* __restrict__ Wkr)
{
    __shared__ float w[64 * 64];
    __shared__ float kin[KT_PAIRS][64];
    const int tid = threadIdx.x;
    const int pair0 = blockIdx.x * KT_PAIRS;

    for (int i = tid; i < 4096; i += 256) w[i] = Wkr[i];
    for (int i = tid; i < KT_PAIRS * 64; i += 256) {
        int p   = pair0 + (i >> 6);
        int row = p >> 4, h = p & 15;
        float tpos = (float)(row & (SEQ_T - 1));
        kin[i >> 6][i & 63] = k[(size_t)row * D_MODEL + h * HEAD_DIM + (i & 63)] * tpos;
    }
    __syncthreads();

    const int o0 = tid * 4;
    const int p  = o0 >> 6;
    const int j0 = o0 & 63;
    float out[4] = {0.f, 0.f, 0.f, 0.f};
    #pragma unroll 8
    for (int i = 0; i < 64; i++) {
        float kv_ = kin[p][i];
        #pragma unroll
        for (int c = 0; c < 4; c++) out[c] += kv_ * w[i * 64 + j0 + c];
    }
    int gp = pair0 + p;
    int row = gp >> 4, h = gp & 15;
    #pragma unroll
    for (int c = 0; c < 4; c++)
        k[(size_t)row * D_MODEL + h * HEAD_DIM + j0 + c] = out[c];
}

// ============ flash attention, split-bf16 mma.sync, causal 64x64 ============
// 128 threads / 4 warps; warp wi owns q-rows [wi*16, wi*16+16).
// smem tiles stride 72 bf16 (144B): Qh Ql Kh Kl Vh Vl.
#define FS 72
#define FA_QH 0
#define FA_QL 4608
#define FA_KH 9216
#define FA_KL 13824
#define FA_VH 18432
#define FA_VL 23040
#define FA_SMEM (27648 * 2)   // 55296 bytes

__global__ __launch_bounds__(128) void flash_attn_mma(
    const __nv_bfloat16* __restrict__ qh, const __nv_bfloat16* __restrict__ ql,
    const __nv_bfloat16* __restrict__ kh, const __nv_bfloat16* __restrict__ kl,
    const __nv_bfloat16* __restrict__ vh, const __nv_bfloat16* __restrict__ vl,
    float* __restrict__ y)
{
    extern __shared__ __align__(16) char smem[];
    const uint32_t sbase = smem_u32(smem);
    const int tid = threadIdx.x;
    const int lid = tid & 31;
    const int wi  = tid >> 5;
    const int it  = gridDim.x - 1 - blockIdx.x;   // big blocks first
    const int h   = blockIdx.y;
    const int b   = blockIdx.z;
    const int qbase = it * 64;

    // stage Q hi/lo (64 x 64 bf16 tiles)
    {
        const __nv_bfloat16* qhp = qh + (size_t)(b * SEQ_T + qbase) * D_MODEL + h * 64;
        const __nv_bfloat16* qlp = ql + (size_t)(b * SEQ_T + qbase) * D_MODEL + h * 64;
        #pragma unroll
        for (int i = 0; i < 4; i++) {
            int u = tid + i * 128;
            int r = u >> 3, c8 = (u & 7) * 8;
            size_t go = (size_t)r * D_MODEL + c8;
            *(uint4*)(smem + (FA_QH + r * FS + c8) * 2) = *(const uint4*)(qhp + go);
            *(uint4*)(smem + (FA_QL + r * FS + c8) * 2) = *(const uint4*)(qlp + go);
        }
    }
    __syncthreads();

    // Q fragments (A operand), 4 k-steps
    uint32_t qhf[4][4], qlf[4][4];
    #pragma unroll
    for (int t = 0; t < 4; t++) {
        int row = wi * 16 + (lid & 15);
        int col = t * 16 + (lid >> 4) * 8;
        ldmx4(sbase + (uint32_t)(FA_QH + row * FS + col) * 2,
              qhf[t][0], qhf[t][1], qhf[t][2], qhf[t][3]);
        ldmx4(sbase + (uint32_t)(FA_QL + row * FS + col) * 2,
              qlf[t][0], qlf[t][1], qlf[t][2], qlf[t][3]);
    }

    float S[8][4], O[8][4];
    #pragma unroll
    for (int ni = 0; ni < 8; ni++)
        #pragma unroll
        for (int e = 0; e < 4; e++) O[ni][e] = 0.f;
    float m0 = -1e30f, m1 = -1e30f, l0 = 0.f, l1 = 0.f;

    const float cs = 0.125f * 1.44269504088896f;   // scale * log2(e)
    const int row0g = qbase + wi * 16 + (lid >> 2);
    const int row1g = row0g + 8;

    for (int jt = 0; jt <= it; jt++) {
        __syncthreads();
        {
            const int kbase = jt * 64;
            size_t base = (size_t)(b * SEQ_T + kbase) * D_MODEL + h * 64;
            #pragma unroll
            for (int i = 0; i < 4; i++) {
                int u = tid + i * 128;
                int r = u >> 3, c8 = (u & 7) * 8;
                size_t go = base + (size_t)r * D_MODEL + c8;
                *(uint4*)(smem + (FA_KH + r * FS + c8) * 2) = *(const uint4*)(kh + go);
                *(uint4*)(smem + (FA_KL + r * FS + c8) * 2) = *(const uint4*)(kl + go);
                *(uint4*)(smem + (FA_VH + r * FS + c8) * 2) = *(const uint4*)(vh + go);
                *(uint4*)(smem + (FA_VL + r * FS + c8) * 2) = *(const uint4*)(vl + go);
            }
        }
        __syncthreads();

        // ---- S = Qh@Kh + Ql@Kh + Qh@Kl ----
        #pragma unroll
        for (int ni = 0; ni < 8; ni++)
            #pragma unroll
            for (int e = 0; e < 4; e++) S[ni][e] = 0.f;
        #pragma unroll
        for (int t = 0; t < 4; t++) {
            uint32_t bf[8][2];
            #pragma unroll
            for (int np = 0; np < 4; np++) {
                int row = np * 16 + ((lid >> 4) & 1) * 8 + (lid & 7);
                int col = t * 16 + ((lid >> 3) & 1) * 8;
                uint32_t r0, r1, r2, r3;
                ldmx4(sbase + (uint32_t)(FA_KH + row * FS + col) * 2, r0, r1, r2, r3);
                bf[2*np][0] = r0; bf[2*np][1] = r1;
                bf[2*np+1][0] = r2; bf[2*np+1][1] = r3;
            }
            #pragma unroll
            for (int ni = 0; ni < 8; ni++) mma16816(S[ni], qhf[t], bf[ni]);
            #pragma unroll
            for (int ni = 0; ni < 8; ni++) mma16816(S[ni], qlf[t], bf[ni]);
            #pragma unroll
            for (int np = 0; np < 4; np++) {
                int row = np * 16 + ((lid >> 4) & 1) * 8 + (lid & 7);
                int col = t * 16 + ((lid >> 3) & 1) * 8;
                uint32_t r0, r1, r2, r3;
                ldmx4(sbase + (uint32_t)(FA_KL + row * FS + col) * 2, r0, r1, r2, r3);
                bf[2*np][0] = r0; bf[2*np][1] = r1;
                bf[2*np+1][0] = r2; bf[2*np+1][1] = r3;
            }
            #pragma unroll
            for (int ni = 0; ni < 8; ni++) mma16816(S[ni], qhf[t], bf[ni]);
        }

        // ---- scale + causal mask + online softmax (exp2 domain) ----
        const int colb = jt * 64 + 2 * (lid & 3);
        const bool diag = (jt == it);
        float mx0 = -1e30f, mx1 = -1e30f;
        #pragma unroll
        for (int ni = 0; ni < 8; ni++) {
            float s0 = S[ni][0] * cs, s1 = S[ni][1] * cs;
            float s2 = S[ni][2] * cs, s3 = S[ni][3] * cs;
            if (diag) {
                int c0 = colb + ni * 8, c1 = c0 + 1;
                if (c0 > row0g) s0 = -1e30f;
                if (c1 > row0g) s1 = -1e30f;
                if (c0 > row1g) s2 = -1e30f;
                if (c1 > row1g) s3 = -1e30f;
            }
            S[ni][0] = s0; S[ni][1] = s1; S[ni][2] = s2; S[ni][3] = s3;
            mx0 = fmaxf(mx0, fmaxf(s0, s1));
            mx1 = fmaxf(mx1, fmaxf(s2, s3));
        }
        mx0 = fmaxf(mx0, __shfl_xor_sync(0xffffffffu, mx0, 1));
        mx0 = fmaxf(mx0, __shfl_xor_sync(0xffffffffu, mx0, 2));
        mx1 = fmaxf(mx1, __shfl_xor_sync(0xffffffffu, mx1, 1));
        mx1 = fmaxf(mx1, __shfl_xor_sync(0xffffffffu, mx1, 2));
        float mn0 = fmaxf(m0, mx0), mn1 = fmaxf(m1, mx1);
        float corr0 = ex2f(m0 - mn0), corr1 = ex2f(m1 - mn1);
        m0 = mn0; m1 = mn1;
        float rs0 = 0.f, rs1 = 0.f;
        #pragma unroll
        for (int ni = 0; ni < 8; ni++) {
            float p0 = ex2f(S[ni][0] - mn0), p1 = ex2f(S[ni][1] - mn0);
            float p2 = ex2f(S[ni][2] - mn1), p3 = ex2f(S[ni][3] - mn1);
            S[ni][0] = p0; S[ni][1] = p1; S[ni][2] = p2; S[ni][3] = p3;
            rs0 += p0 + p1; rs1 += p2 + p3;
        }
        rs0 += __shfl_xor_sync(0xffffffffu, rs0, 1);
        rs0 += __shfl_xor_sync(0xffffffffu, rs0, 2);
        rs1 += __shfl_xor_sync(0xffffffffu, rs1, 1);
        rs1 += __shfl_xor_sync(0xffffffffu, rs1, 2);
        l0 = l0 * corr0 + rs0;
        l1 = l1 * corr1 + rs1;
        #pragma unroll
        for (int ni = 0; ni < 8; ni++) {
            O[ni][0] *= corr0; O[ni][1] *= corr0;
            O[ni][2] *= corr1; O[ni][3] *= corr1;
        }

        // ---- pack P into A fragments (hi + residual lo), in registers ----
        uint32_t pha[4][4], pla[4][4];
        #pragma unroll
        for (int t = 0; t < 4; t++) {
            int j0 = 2 * t, j1 = 2 * t + 1;
            float pf[4][2] = {{S[j0][0], S[j0][1]}, {S[j0][2], S[j0][3]},
                              {S[j1][0], S[j1][1]}, {S[j1][2], S[j1][3]}};
            #pragma unroll
            for (int e = 0; e < 4; e++) {
                uint32_t rh = packbf(pf[e][0], pf[e][1]);
                float flo = __uint_as_float(rh << 16);
                float fhi = __uint_as_float(rh & 0xFFFF0000u);
                pha[t][e] = rh;
                pla[t][e] = packbf(pf[e][0] - flo, pf[e][1] - fhi);
            }
        }

        // ---- O += Ph@Vh + Pl@Vh + Ph@Vl ----
        #pragma unroll
        for (int t = 0; t < 4; t++) {
            uint32_t vb[8][2];
            #pragma unroll
            for (int dp = 0; dp < 4; dp++) {
                int row = t * 16 + (lid & 15);
                int col = dp * 16 + (lid >> 4) * 8;
                uint32_t r0, r1, r2, r3;
                ldmx4t(sbase + (uint32_t)(FA_VH + row * FS + col) * 2, r0, r1, r2, r3);
                vb[2*dp][0] = r0; vb[2*dp][1] = r1;
                vb[2*dp+1][0] = r2; vb[2*dp+1][1] = r3;
            }
            #pragma unroll
            for (int ni = 0; ni < 8; ni++) mma16816(O[ni], pha[t], vb[ni]);
            #pragma unroll
            for (int ni = 0; ni < 8; ni++) mma16816(O[ni], pla[t], vb[ni]);
            #pragma unroll
            for (int dp = 0; dp < 4; dp++) {
                int row = t * 16 + (lid & 15);
                int col = dp * 16 + (lid >> 4) * 8;
                uint32_t r0, r1, r2, r3;
                ldmx4t(sbase + (uint32_t)(FA_VL + row * FS + col) * 2, r0, r1, r2, r3);
                vb[2*dp][0] = r0; vb[2*dp][1] = r1;
                vb[2*dp+1][0] = r2; vb[2*dp+1][1] = r3;
            }
            #pragma unroll
            for (int ni = 0; ni < 8; ni++) mma16816(O[ni], pha[t], vb[ni]);
        }
    }

    // ---- epilogue ----
    float inv0 = 1.f / l0, inv1 = 1.f / l1;
    float* yp = y + (size_t)(b * SEQ_T + qbase + wi * 16) * D_MODEL + h * 64;
    const int gr = lid >> 2, gc = 2 * (lid & 3);
    #pragma unroll
    for (int ni = 0; ni < 8; ni++) {
        *(float2*)(yp + (size_t)gr * D_MODEL + ni * 8 + gc) =
            make_float2(O[ni][0] * inv0, O[ni][1] * inv0);
        *(float2*)(yp + (size_t)(gr + 8) * D_MODEL + ni * 8 + gc) =
            make_float2(O[ni][2] * inv1, O[ni][3] * inv1);
    }
}

// ===================== launch ===============================================
extern "C" void kernel_launch(void* const* d_in, const int* in_sizes, int n_in,
                              void* d_out, int out_size)
{
    const float* x   = (const float*)d_in[0];
    // d_in[1] = mask (causal, static — ignored)
    const float* Wq  = (const float*)d_in[2];
    const float* bq  = (const float*)d_in[3];
    const float* Wkv = (const float*)d_in[4];
    const float* bkv = (const float*)d_in[5];
    const float* Wk  = (const float*)d_in[6];
    const float* bk  = (const float*)d_in[7];
    const float* Wv  = (const float*)d_in[8];
    const float* bv  = (const float*)d_in[9];
    const float* Wo  = (const float*)d_in[10];
    const float* bo  = (const float*)d_in[11];
    const float* Wkr = (const float*)d_in[12];
    float* out = (float*)d_out;

    float *kv, *q, *k, *v, *y;
    cudaGetSymbolAddress((void**)&kv, g_kv);
    cudaGetSymbolAddress((void**)&q,  g_q);
    cudaGetSymbolAddress((void**)&k,  g_k);
    cudaGetSymbolAddress((void**)&v,  g_v);
    cudaGetSymbolAddress((void**)&y,  g_y);
    __nv_bfloat16 *xh, *xl, *kvh, *kvl, *yh, *yl;
    __nv_bfloat16 *qh, *ql, *kh2, *kl2, *vh2, *vl2;
    __nv_bfloat16 *Wqh, *Wql, *Wkvh, *Wkvl, *Wkh, *Wkl, *Wvh, *Wvl, *Woh, *Wol;
    cudaGetSymbolAddress((void**)&xh,  g_xh);   cudaGetSymbolAddress((void**)&xl,  g_xl);
    cudaGetSymbolAddress((void**)&kvh, g_kvh);  cudaGetSymbolAddress((void**)&kvl, g_kvl);
    cudaGetSymbolAddress((void**)&yh,  g_yh);   cudaGetSymbolAddress((void**)&yl,  g_yl);
    cudaGetSymbolAddress((void**)&qh,  g_qh);   cudaGetSymbolAddress((void**)&ql,  g_ql);
    cudaGetSymbolAddress((void**)&kh2, g_kh2);  cudaGetSymbolAddress((void**)&kl2, g_kl2);
    cudaGetSymbolAddress((void**)&vh2, g_vh2);  cudaGetSymbolAddress((void**)&vl2, g_vl2);
    cudaGetSymbolAddress((void**)&Wqh, g_Wqh);  cudaGetSymbolAddress((void**)&Wql, g_Wql);
    cudaGetSymbolAddress((void**)&Wkvh,g_Wkvh); cudaGetSymbolAddress((void**)&Wkvl,g_Wkvl);
    cudaGetSymbolAddress((void**)&Wkh, g_Wkh);  cudaGetSymbolAddress((void**)&Wkl, g_Wkl);
    cudaGetSymbolAddress((void**)&Wvh, g_Wvh);  cudaGetSymbolAddress((void**)&Wvl, g_Wvl);
    cudaGetSymbolAddress((void**)&Woh, g_Woh);  cudaGetSymbolAddress((void**)&Wol, g_Wol);

    cudaFuncSetAttribute(gemm_mma, cudaFuncAttributeMaxDynamicSharedMemorySize, GEMM_SMEM);
    cudaFuncSetAttribute(flash_attn_mma, cudaFuncAttributeMaxDynamicSharedMemorySize, FA_SMEM);

    // weight transpose+split
    wsplit_t<<<dim3(D_MODEL/32, D_MODEL/32), 256>>>(Wq,  Wqh,  Wql,  D_MODEL, D_MODEL);
    wsplit_t<<<dim3(KV_DIM/32,  D_MODEL/32), 256>>>(Wkv, Wkvh, Wkvl, D_MODEL, KV_DIM);
    wsplit_t<<<dim3(D_MODEL/32, KV_DIM/32),  256>>>(Wk,  Wkh,  Wkl,  KV_DIM,  D_MODEL);
    wsplit_t<<<dim3(D_MODEL/32, KV_DIM/32),  256>>>(Wv,  Wvh,  Wvl,  KV_DIM,  D_MODEL);
    wsplit_t<<<dim3(D_MODEL/32, D_MODEL/32), 256>>>(Wo,  Woh,  Wol,  D_MODEL, D_MODEL);
    fsplit<<<(ROWS * D_MODEL) / 256, 256>>>(x, xh, xl, ROWS * D_MODEL);

    // projections
    gemm_mma<<<dim3(KV_DIM/128, ROWS/128), 256, GEMM_SMEM>>>(xh, xl, Wkvh, Wkvl, bkv, kv, D_MODEL, KV_DIM);
    fsplit<<<(ROWS * KV_DIM) / 256, 256>>>(kv, kvh, kvl, ROWS * KV_DIM);
    gemm_mma<<<dim3(D_MODEL/128, ROWS/128), 256, GEMM_SMEM>>>(xh, xl, Wqh, Wql, bq, q, D_MODEL, D_MODEL);
    gemm_mma<<<dim3(D_MODEL/128, ROWS/128), 256, GEMM_SMEM>>>(kvh, kvl, Wkh, Wkl, bk, k, KV_DIM, D_MODEL);
    gemm_mma<<<dim3(D_MODEL/128, ROWS/128), 256, GEMM_SMEM>>>(kvh, kvl, Wvh, Wvl, bv, v, KV_DIM, D_MODEL);

    // position transforms
    rope_q_kernel<<<(ROWS * N_HEADS * 32) / 256, 256>>>(q);
    k_transform_kernel<<<(ROWS * N_HEADS) / KT_PAIRS, 256>>>(k, Wkr);

    // attention operand splits
    fsplit<<<(ROWS * D_MODEL) / 256, 256>>>(q, qh, ql, ROWS * D_MODEL);
    fsplit<<<(ROWS * D_MODEL) / 256, 256>>>(k, kh2, kl2, ROWS * D_MODEL);
    fsplit<<<(ROWS * D_MODEL) / 256, 256>>>(v, vh2, vl2, ROWS * D_MODEL);

    // attention (tensor path)
    flash_attn_mma<<<dim3(SEQ_T / 64, N_HEADS, BATCH), 128, FA_SMEM>>>(
        qh, ql, kh2, kl2, vh2, vl2, y);

    // output projection
    fsplit<<<(ROWS * D_MODEL) / 256, 256>>>(y, yh, yl, ROWS * D_MODEL);
    gemm_mma<<<dim3(D_MODEL/128, ROWS/128), 256, GEMM_SMEM>>>(yh, yl, Woh, Wol, bo, out, D_MODEL, D_MODEL);
}

// round 13
// speedup vs baseline: 4.2797x; 1.0873x over previous
#include <cuda_runtime.h>
#include <cuda_bf16.h>
#include <math.h>
#include <cstdint>

#define D_MODEL 1024
#define N_HEADS 16
#define HEAD_DIM 64
#define KV_DIM 256
#define SEQ_T 2048
#define BATCH 2
#define ROWS (BATCH * SEQ_T)   // 4096

// ===================== scratch (device globals) =============================
__device__ float g_q [ROWS * D_MODEL];
__device__ float g_k [ROWS * D_MODEL];
__device__ float g_out_unused[4];   // (placeholder, keeps symbol layout simple)

__device__ __align__(16) __nv_bfloat16 g_xh [ROWS * D_MODEL];
__device__ __align__(16) __nv_bfloat16 g_xl [ROWS * D_MODEL];
__device__ __align__(16) __nv_bfloat16 g_kvh[ROWS * KV_DIM];
__device__ __align__(16) __nv_bfloat16 g_kvl[ROWS * KV_DIM];
__device__ __align__(16) __nv_bfloat16 g_yh [ROWS * D_MODEL];
__device__ __align__(16) __nv_bfloat16 g_yl [ROWS * D_MODEL];
__device__ __align__(16) __nv_bfloat16 g_qh [ROWS * D_MODEL];
__device__ __align__(16) __nv_bfloat16 g_ql [ROWS * D_MODEL];
__device__ __align__(16) __nv_bfloat16 g_kh2[ROWS * D_MODEL];
__device__ __align__(16) __nv_bfloat16 g_kl2[ROWS * D_MODEL];
__device__ __align__(16) __nv_bfloat16 g_vh2[ROWS * D_MODEL];
__device__ __align__(16) __nv_bfloat16 g_vl2[ROWS * D_MODEL];
// transposed weights [N][K], bf16 hi/lo
__device__ __align__(16) __nv_bfloat16 g_Wqh [D_MODEL * D_MODEL];
__device__ __align__(16) __nv_bfloat16 g_Wql [D_MODEL * D_MODEL];
__device__ __align__(16) __nv_bfloat16 g_Wkvh[KV_DIM * D_MODEL];
__device__ __align__(16) __nv_bfloat16 g_Wkvl[KV_DIM * D_MODEL];
__device__ __align__(16) __nv_bfloat16 g_Wkh [D_MODEL * KV_DIM];
__device__ __align__(16) __nv_bfloat16 g_Wkl [D_MODEL * KV_DIM];
__device__ __align__(16) __nv_bfloat16 g_Wvh [D_MODEL * KV_DIM];
__device__ __align__(16) __nv_bfloat16 g_Wvl [D_MODEL * KV_DIM];
__device__ __align__(16) __nv_bfloat16 g_Woh [D_MODEL * D_MODEL];
__device__ __align__(16) __nv_bfloat16 g_Wol [D_MODEL * D_MODEL];

// ===================== small helpers ========================================
__device__ __forceinline__ uint32_t smem_u32(const void* p) {
    uint32_t a;
    asm("{ .reg .u64 t; cvta.to.shared.u64 t, %1; cvt.u32.u64 %0, t; }"
        : "=r"(a) : "l"(p));
    return a;
}
__device__ __forceinline__ float ex2f(float x) {
    float y; asm("ex2.approx.f32 %0, %1;" : "=f"(y) : "f"(x)); return y;
}
// pack (lo, hi) floats -> bf16x2 (lo in low half)
__device__ __forceinline__ uint32_t packbf(float lo, float hi) {
    uint32_t r; asm("cvt.rn.bf16x2.f32 %0, %1, %2;" : "=r"(r) : "f"(hi), "f"(lo));
    return r;
}
// split two floats into (hi bf16x2, lo bf16x2)
__device__ __forceinline__ void split2(float v0, float v1, uint32_t& h, uint32_t& l) {
    h = packbf(v0, v1);
    float f0 = __uint_as_float(h << 16);
    float f1 = __uint_as_float(h & 0xFFFF0000u);
    l = packbf(v0 - f0, v1 - f1);
}

__device__ __forceinline__ void ldmx4(uint32_t addr, uint32_t& r0, uint32_t& r1,
                                      uint32_t& r2, uint32_t& r3)
{
    asm volatile("ldmatrix.sync.aligned.m8n8.x4.shared.b16 {%0,%1,%2,%3}, [%4];"
        : "=r"(r0), "=r"(r1), "=r"(r2), "=r"(r3) : "r"(addr));
}
__device__ __forceinline__ void ldmx4t(uint32_t addr, uint32_t& r0, uint32_t& r1,
                                       uint32_t& r2, uint32_t& r3)
{
    asm volatile("ldmatrix.sync.aligned.m8n8.x4.trans.shared.b16 {%0,%1,%2,%3}, [%4];"
        : "=r"(r0), "=r"(r1), "=r"(r2), "=r"(r3) : "r"(addr));
}
__device__ __forceinline__ void mma16816(float* d, const uint32_t* a, const uint32_t* b)
{
    asm volatile(
        "mma.sync.aligned.m16n8k16.row.col.f32.bf16.bf16.f32 "
        "{%0,%1,%2,%3}, {%4,%5,%6,%7}, {%8,%9}, {%0,%1,%2,%3};"
        : "+f"(d[0]), "+f"(d[1]), "+f"(d[2]), "+f"(d[3])
        : "r"(a[0]), "r"(a[1]), "r"(a[2]), "r"(a[3]), "r"(b[0]), "r"(b[1]));
}

// ===================== conversion kernels ===================================
// vectorized split: 4 elements / thread
__global__ void fsplit4(const float* __restrict__ X,
                        __nv_bfloat16* __restrict__ H, __nv_bfloat16* __restrict__ L,
                        int n4)
{
    int i = blockIdx.x * blockDim.x + threadIdx.x;
    if (i >= n4) return;
    float4 v = *(const float4*)(X + 4 * (size_t)i);
    uint32_t h0, l0, h1, l1;
    split2(v.x, v.y, h0, l0);
    split2(v.z, v.w, h1, l1);
    *(uint2*)(H + 4 * (size_t)i) = make_uint2(h0, h1);
    *(uint2*)(L + 4 * (size_t)i) = make_uint2(l0, l1);
}

// W[K][N] fp32 -> Th/Tl[N][K] bf16 (transpose + split)
__global__ __launch_bounds__(256) void wsplit_t(
    const float* __restrict__ W,
    __nv_bfloat16* __restrict__ Th, __nv_bfloat16* __restrict__ Tl,
    int K, int N)
{
    __shared__ float t[32][33];
    const int n0 = blockIdx.x * 32, k0 = blockIdx.y * 32;
    const int tx = threadIdx.x & 31, ty = threadIdx.x >> 5;
    #pragma unroll
    for (int i = 0; i < 4; i++)
        t[ty + i * 8][tx] = W[(size_t)(k0 + ty + i * 8) * N + n0 + tx];
    __syncthreads();
    #pragma unroll
    for (int i = 0; i < 4; i++) {
        float v = t[tx][ty + i * 8];
        __nv_bfloat16 h = __float2bfloat16(v);
        __nv_bfloat16 l = __float2bfloat16(v - __bfloat162float(h));
        size_t o = (size_t)(n0 + ty + i * 8) * K + k0 + tx;
        Th[o] = h; Tl[o] = l;
    }
}

// ===================== mma.sync GEMM (R8-proven + split epilogue) ===========
#define LDS_ 72
#define STAGE_BYTES (2 * 9216 * 2)
#define GEMM_SMEM (2 * STAGE_BYTES)

__global__ __launch_bounds__(256) void gemm_mma(
    const __nv_bfloat16* __restrict__ Ah, const __nv_bfloat16* __restrict__ Al,
    const __nv_bfloat16* __restrict__ Bh, const __nv_bfloat16* __restrict__ Bl,
    const float* __restrict__ bias, float* __restrict__ C,
    __nv_bfloat16* __restrict__ Ch, __nv_bfloat16* __restrict__ Cl,
    int K, int N)
{
    extern __shared__ __align__(16) char smem[];
    const uint32_t sbase = smem_u32(smem);
    const int tid = threadIdx.x;
    const int lid = tid & 31;
    const int wid = tid >> 5;
    const int wm = wid >> 2;
    const int wn = wid & 3;
    const int bm = blockIdx.y * 128;
    const int bn = blockIdx.x * 128;

    float acc[4][4][4];
    #pragma unroll
    for (int mi = 0; mi < 4; mi++)
        #pragma unroll
        for (int ni = 0; ni < 4; ni++)
            #pragma unroll
            for (int e = 0; e < 4; e++) acc[mi][ni][e] = 0.f;

    const int nkc = K >> 6;
    const int total = 3 * nkc;

    auto issue = [&](int cc, int s) {
        int p  = cc / nkc;
        int kc = cc - p * nkc;
        const __nv_bfloat16* Ap = ((p == 1) ? Al : Ah) + (size_t)bm * K + kc * 64;
        const __nv_bfloat16* Bp = ((p == 2) ? Bl : Bh) + (size_t)bn * K + kc * 64;
        uint32_t sa = sbase + s * STAGE_BYTES;
        uint32_t sb = sa + 9216 * 2;
        #pragma unroll
        for (int i = 0; i < 4; i++) {
            int c = tid + i * 256;
            int r = c >> 3, e = (c & 7) * 8;
            asm volatile("cp.async.cg.shared.global [%0], [%1], 16;"
                :: "r"(sa + (uint32_t)(r * LDS_ + e) * 2), "l"(Ap + (size_t)r * K + e));
        }
        #pragma unroll
        for (int i = 0; i < 4; i++) {
            int c = tid + i * 256;
            int r = c >> 3, e = (c & 7) * 8;
            asm volatile("cp.async.cg.shared.global [%0], [%1], 16;"
                :: "r"(sb + (uint32_t)(r * LDS_ + e) * 2), "l"(Bp + (size_t)r * K + e));
        }
        asm volatile("cp.async.commit_group;");
    };

    issue(0, 0);

    for (int cc = 0; cc < total; cc++) {
        if (cc + 1 < total) {
            issue(cc + 1, (cc + 1) & 1);
            asm volatile("cp.async.wait_group 1;");
        } else {
            asm volatile("cp.async.wait_group 0;");
        }
        __syncthreads();

        uint32_t sa = sbase + (cc & 1) * STAGE_BYTES;
        uint32_t sb = sa + 9216 * 2;
        #pragma unroll
        for (int ks = 0; ks < 4; ks++) {
            uint32_t a[4][4];
            #pragma unroll
            for (int mi = 0; mi < 4; mi++) {
                int row = wm * 64 + mi * 16 + (lid & 15);
                int col = ks * 16 + (lid >> 4) * 8;
                ldmx4(sa + (uint32_t)(row * LDS_ + col) * 2,
                      a[mi][0], a[mi][1], a[mi][2], a[mi][3]);
            }
            uint32_t b[4][2];
            #pragma unroll
            for (int np = 0; np < 2; np++) {
                int row = wn * 32 + np * 16 + ((lid >> 4) & 1) * 8 + (lid & 7);
                int col = ks * 16 + ((lid >> 3) & 1) * 8;
                uint32_t r0, r1, r2, r3;
                ldmx4(sb + (uint32_t)(row * LDS_ + col) * 2, r0, r1, r2, r3);
                b[2 * np][0] = r0; b[2 * np][1] = r1;
                b[2 * np + 1][0] = r2; b[2 * np + 1][1] = r3;
            }
            #pragma unroll
            for (int mi = 0; mi < 4; mi++)
                #pragma unroll
                for (int ni = 0; ni < 4; ni++)
                    mma16816(acc[mi][ni], a[mi], b[ni]);
        }
        __syncthreads();
    }

    const int gr = lid >> 2;
    const int gc = (lid & 3) * 2;
    #pragma unroll
    for (int mi = 0; mi < 4; mi++) {
        #pragma unroll
        for (int ni = 0; ni < 4; ni++) {
            int row0 = bm + wm * 64 + mi * 16 + gr;
            int col0 = bn + wn * 32 + ni * 8 + gc;
            float2 b01 = *(const float2*)(bias + col0);
            float v00 = acc[mi][ni][0] + b01.x, v01 = acc[mi][ni][1] + b01.y;
            float v10 = acc[mi][ni][2] + b01.x, v11 = acc[mi][ni][3] + b01.y;
            if (C) {
                *(float2*)(C + (size_t)row0 * N + col0) = make_float2(v00, v01);
                *(float2*)(C + (size_t)(row0 + 8) * N + col0) = make_float2(v10, v11);
            }
            if (Ch) {
                uint32_t h, l;
                split2(v00, v01, h, l);
                *(uint32_t*)(Ch + (size_t)row0 * N + col0) = h;
                *(uint32_t*)(Cl + (size_t)row0 * N + col0) = l;
                split2(v10, v11, h, l);
                *(uint32_t*)(Ch + (size_t)(row0 + 8) * N + col0) = h;
                *(uint32_t*)(Cl + (size_t)(row0 + 8) * N + col0) = l;
            }
        }
    }
}

// ============ RoPE on q: read fp32, write split bf16 ========================
__global__ void rope_q_split(const float* __restrict__ q,
                             __nv_bfloat16* __restrict__ qh,
                             __nv_bfloat16* __restrict__ ql)
{
    int idx = blockIdx.x * blockDim.x + threadIdx.x;
    if (idx >= ROWS * N_HEADS * 32) return;
    int d   = idx & 31;
    int h   = (idx >> 5) & 15;
    int row = idx >> 9;
    int t   = row & (SEQ_T - 1);
    float inv = powf(10000.0f, -(float)d / 32.0f);
    float ang = (float)t * inv;
    float s, c;
    sincosf(ang, &s, &c);
    size_t o = (size_t)row * D_MODEL + h * HEAD_DIM + d;
    float q1 = q[o], q2 = q[o + 32];
    float r1 = q1 * c - q2 * s;
    float r2 = q2 * c + q1 * s;
    __nv_bfloat16 h1 = __float2bfloat16(r1);
    __nv_bfloat16 h2 = __float2bfloat16(r2);
    qh[o]      = h1;  ql[o]      = __float2bfloat16(r1 - __bfloat162float(h1));
    qh[o + 32] = h2;  ql[o + 32] = __float2bfloat16(r2 - __bfloat162float(h2));
}

// ========== k' = (k * t) @ Wkr per (row, head): write split bf16 ============
#define KT_PAIRS 16
__global__ __launch_bounds__(256) void k_transform_split(
    const float* __restrict__ k, const float* __restrict__ Wkr,
    __nv_bfloat16* __restrict__ kh, __nv_bfloat16* __restrict__ kl)
{
    __shared__ float w[64 * 64];
    __shared__ float kin[KT_PAIRS][64];
    const int tid = threadIdx.x;
    const int pair0 = blockIdx.x * KT_PAIRS;

    for (int i = tid; i < 4096; i += 256) w[i] = Wkr[i];
    for (int i = tid; i < KT_PAIRS * 64; i += 256) {
        int p   = pair0 + (i >> 6);
        int row = p >> 4, h = p & 15;
        float tpos = (float)(row & (SEQ_T - 1));
        kin[i >> 6][i & 63] = k[(size_t)row * D_MODEL + h * HEAD_DIM + (i & 63)] * tpos;
    }
    __syncthreads();

    const int o0 = tid * 4;
    const int p  = o0 >> 6;
    const int j0 = o0 & 63;
    float out[4] = {0.f, 0.f, 0.f, 0.f};
    #pragma unroll 8
    for (int i = 0; i < 64; i++) {
        float kv_ = kin[p][i];
        #pragma unroll
        for (int c = 0; c < 4; c++) out[c] += kv_ * w[i * 64 + j0 + c];
    }
    int gp = pair0 + p;
    int row = gp >> 4, h = gp & 15;
    uint32_t h0, l0, h1, l1;
    split2(out[0], out[1], h0, l0);
    split2(out[2], out[3], h1, l1);
    size_t o = (size_t)row * D_MODEL + h * HEAD_DIM + j0;
    *(uint2*)(kh + o) = make_uint2(h0, h1);
    *(uint2*)(kl + o) = make_uint2(l0, l1);
}

// ============ flash attention, split-bf16 mma.sync, cp.async pipe ===========
// 128 threads / 4 warps; warp wi owns q-rows [wi*16, wi*16+16).
// smem bf16 tiles stride 72: QH, QL fixed; KV double-buffered (KH KL VH VL).
#define FS 72
#define FA_QH 0
#define FA_QL 4608
#define FA_KV0 9216
#define KV_TILE 4608                 // elements per tile (64*72)
#define KV_BUF  (4 * KV_TILE)        // KH KL VH VL
#define FA_SMEM ((FA_KV0 + 2 * KV_BUF) * 2)   // 92160 bytes

__global__ __launch_bounds__(128) void flash_attn_mma(
    const __nv_bfloat16* __restrict__ qh, const __nv_bfloat16* __restrict__ ql,
    const __nv_bfloat16* __restrict__ kh, const __nv_bfloat16* __restrict__ kl,
    const __nv_bfloat16* __restrict__ vh, const __nv_bfloat16* __restrict__ vl,
    __nv_bfloat16* __restrict__ yh, __nv_bfloat16* __restrict__ yl)
{
    extern __shared__ __align__(16) char smem[];
    const uint32_t sbase = smem_u32(smem);
    const int tid = threadIdx.x;
    const int lid = tid & 31;
    const int wi  = tid >> 5;
    const int it  = gridDim.x - 1 - blockIdx.x;   // big blocks first
    const int h   = blockIdx.y;
    const int b   = blockIdx.z;
    const int qbase = it * 64;

    // cp.async loader for KV tiles of block jt into buffer s
    auto issue_kv = [&](int jt, int s) {
        size_t base = (size_t)(b * SEQ_T + jt * 64) * D_MODEL + h * 64;
        uint32_t sb0 = sbase + (uint32_t)(FA_KV0 + s * KV_BUF) * 2;
        #pragma unroll
        for (int i = 0; i < 4; i++) {
            int u = tid + i * 128;
            int r = u >> 3, c8 = (u & 7) * 8;
            size_t go = base + (size_t)r * D_MODEL + c8;
            uint32_t so = (uint32_t)(r * FS + c8) * 2;
            asm volatile("cp.async.cg.shared.global [%0], [%1], 16;"
                :: "r"(sb0 + 0 * KV_TILE * 2 + so), "l"(kh + go));
            asm volatile("cp.async.cg.shared.global [%0], [%1], 16;"
                :: "r"(sb0 + 1 * KV_TILE * 2 + so), "l"(kl + go));
            asm volatile("cp.async.cg.shared.global [%0], [%1], 16;"
                :: "r"(sb0 + 2 * KV_TILE * 2 + so), "l"(vh + go));
            asm volatile("cp.async.cg.shared.global [%0], [%1], 16;"
                :: "r"(sb0 + 3 * KV_TILE * 2 + so), "l"(vl + go));
        }
        asm volatile("cp.async.commit_group;");
    };

    issue_kv(0, 0);

    // stage Q hi/lo (64 x 64 bf16 tiles)
    {
        const __nv_bfloat16* qhp = qh + (size_t)(b * SEQ_T + qbase) * D_MODEL + h * 64;
        const __nv_bfloat16* qlp = ql + (size_t)(b * SEQ_T + qbase) * D_MODEL + h * 64;
        #pragma unroll
        for (int i = 0; i < 4; i++) {
            int u = tid + i * 128;
            int r = u >> 3, c8 = (u & 7) * 8;
            size_t go = (size_t)r * D_MODEL + c8;
            *(uint4*)(smem + (FA_QH + r * FS + c8) * 2) = *(const uint4*)(qhp + go);
            *(uint4*)(smem + (FA_QL + r * FS + c8) * 2) = *(const uint4*)(qlp + go);
        }
    }
    __syncthreads();

    uint32_t qhf[4][4], qlf[4][4];
    #pragma unroll
    for (int t = 0; t < 4; t++) {
        int row = wi * 16 + (lid & 15);
        int col = t * 16 + (lid >> 4) * 8;
        ldmx4(sbase + (uint32_t)(FA_QH + row * FS + col) * 2,
              qhf[t][0], qhf[t][1], qhf[t][2], qhf[t][3]);
        ldmx4(sbase + (uint32_t)(FA_QL + row * FS + col) * 2,
              qlf[t][0], qlf[t][1], qlf[t][2], qlf[t][3]);
    }

    float S[8][4], O[8][4];
    #pragma unroll
    for (int ni = 0; ni < 8; ni++)
        #pragma unroll
        for (int e = 0; e < 4; e++) O[ni][e] = 0.f;
    float m0 = -1e30f, m1 = -1e30f, l0 = 0.f, l1 = 0.f;

    const float cs = 0.125f * 1.44269504088896f;
    const int row0g = qbase + wi * 16 + (lid >> 2);
    const int row1g = row0g + 8;

    for (int jt = 0; jt <= it; jt++) {
        if (jt < it) {
            issue_kv(jt + 1, (jt + 1) & 1);
            asm volatile("cp.async.wait_group 1;");
        } else {
            asm volatile("cp.async.wait_group 0;");
        }
        __syncthreads();

        const uint32_t KB = (uint32_t)(FA_KV0 + (jt & 1) * KV_BUF);
        const uint32_t S_KH = KB, S_KL = KB + KV_TILE;
        const uint32_t S_VH = KB + 2 * KV_TILE, S_VL = KB + 3 * KV_TILE;

        // ---- S = Qh@Kh + Ql@Kh + Qh@Kl ----
        #pragma unroll
        for (int ni = 0; ni < 8; ni++)
            #pragma unroll
            for (int e = 0; e < 4; e++) S[ni][e] = 0.f;
        #pragma unroll
        for (int t = 0; t < 4; t++) {
            uint32_t bf[8][2];
            #pragma unroll
            for (int np = 0; np < 4; np++) {
                int row = np * 16 + ((lid >> 4) & 1) * 8 + (lid & 7);
                int col = t * 16 + ((lid >> 3) & 1) * 8;
                uint32_t r0, r1, r2, r3;
                ldmx4(sbase + (S_KH + row * FS + col) * 2, r0, r1, r2, r3);
                bf[2*np][0] = r0; bf[2*np][1] = r1;
                bf[2*np+1][0] = r2; bf[2*np+1][1] = r3;
            }
            #pragma unroll
            for (int ni = 0; ni < 8; ni++) mma16816(S[ni], qhf[t], bf[ni]);
            #pragma unroll
            for (int ni = 0; ni < 8; ni++) mma16816(S[ni], qlf[t], bf[ni]);
            #pragma unroll
            for (int np = 0; np < 4; np++) {
                int row = np * 16 + ((lid >> 4) & 1) * 8 + (lid & 7);
                int col = t * 16 + ((lid >> 3) & 1) * 8;
                uint32_t r0, r1, r2, r3;
                ldmx4(sbase + (S_KL + row * FS + col) * 2, r0, r1, r2, r3);
                bf[2*np][0] = r0; bf[2*np][1] = r1;
                bf[2*np+1][0] = r2; bf[2*np+1][1] = r3;
            }
            #pragma unroll
            for (int ni = 0; ni < 8; ni++) mma16816(S[ni], qhf[t], bf[ni]);
        }

        // ---- scale + causal mask + online softmax (exp2 domain) ----
        const int colb = jt * 64 + 2 * (lid & 3);
        const bool diag = (jt == it);
        float mx0 = -1e30f, mx1 = -1e30f;
        #pragma unroll
        for (int ni = 0; ni < 8; ni++) {
            float s0 = S[ni][0] * cs, s1 = S[ni][1] * cs;
            float s2 = S[ni][2] * cs, s3 = S[ni][3] * cs;
            if (diag) {
                int c0 = colb + ni * 8, c1 = c0 + 1;
                if (c0 > row0g) s0 = -1e30f;
                if (c1 > row0g) s1 = -1e30f;
                if (c0 > row1g) s2 = -1e30f;
                if (c1 > row1g) s3 = -1e30f;
            }
            S[ni][0] = s0; S[ni][1] = s1; S[ni][2] = s2; S[ni][3] = s3;
            mx0 = fmaxf(mx0, fmaxf(s0, s1));
            mx1 = fmaxf(mx1, fmaxf(s2, s3));
        }
        mx0 = fmaxf(mx0, __shfl_xor_sync(0xffffffffu, mx0, 1));
        mx0 = fmaxf(mx0, __shfl_xor_sync(0xffffffffu, mx0, 2));
        mx1 = fmaxf(mx1, __shfl_xor_sync(0xffffffffu, mx1, 1));
        mx1 = fmaxf(mx1, __shfl_xor_sync(0xffffffffu, mx1, 2));
        float mn0 = fmaxf(m0, mx0), mn1 = fmaxf(m1, mx1);
        float corr0 = ex2f(m0 - mn0), corr1 = ex2f(m1 - mn1);
        m0 = mn0; m1 = mn1;
        float rs0 = 0.f, rs1 = 0.f;
        #pragma unroll
        for (int ni = 0; ni < 8; ni++) {
            float p0 = ex2f(S[ni][0] - mn0), p1 = ex2f(S[ni][1] - mn0);
            float p2 = ex2f(S[ni][2] - mn1), p3 = ex2f(S[ni][3] - mn1);
            S[ni][0] = p0; S[ni][1] = p1; S[ni][2] = p2; S[ni][3] = p3;
            rs0 += p0 + p1; rs1 += p2 + p3;
        }
        rs0 += __shfl_xor_sync(0xffffffffu, rs0, 1);
        rs0 += __shfl_xor_sync(0xffffffffu, rs0, 2);
        rs1 += __shfl_xor_sync(0xffffffffu, rs1, 1);
        rs1 += __shfl_xor_sync(0xffffffffu, rs1, 2);
        l0 = l0 * corr0 + rs0;
        l1 = l1 * corr1 + rs1;
        #pragma unroll
        for (int ni = 0; ni < 8; ni++) {
            O[ni][0] *= corr0; O[ni][1] *= corr0;
            O[ni][2] *= corr1; O[ni][3] *= corr1;
        }

        // ---- pack P into A fragments (hi + residual lo) ----
        uint32_t pha[4][4], pla[4][4];
        #pragma unroll
        for (int t = 0; t < 4; t++) {
            int j0 = 2 * t, j1 = 2 * t + 1;
            float pf[4][2] = {{S[j0][0], S[j0][1]}, {S[j0][2], S[j0][3]},
                              {S[j1][0], S[j1][1]}, {S[j1][2], S[j1][3]}};
            #pragma unroll
            for (int e = 0; e < 4; e++)
                split2(pf[e][0], pf[e][1], pha[t][e], pla[t][e]);
        }

        // ---- O += Ph@Vh + Pl@Vh + Ph@Vl ----
        #pragma unroll
        for (int t = 0; t < 4; t++) {
            uint32_t vb[8][2];
            #pragma unroll
            for (int dp = 0; dp < 4; dp++) {
                int row = t * 16 + (lid & 15);
                int col = dp * 16 + (lid >> 4) * 8;
                uint32_t r0, r1, r2, r3;
                ldmx4t(sbase + (S_VH + row * FS + col) * 2, r0, r1, r2, r3);
                vb[2*dp][0] = r0; vb[2*dp][1] = r1;
                vb[2*dp+1][0] = r2; vb[2*dp+1][1] = r3;
            }
            #pragma unroll
            for (int ni = 0; ni < 8; ni++) mma16816(O[ni], pha[t], vb[ni]);
            #pragma unroll
            for (int ni = 0; ni < 8; ni++) mma16816(O[ni], pla[t], vb[ni]);
            #pragma unroll
            for (int dp = 0; dp < 4; dp++) {
                int row = t * 16 + (lid & 15);
                int col = dp * 16 + (lid >> 4) * 8;
                uint32_t r0, r1, r2, r3;
                ldmx4t(sbase + (S_VL + row * FS + col) * 2, r0, r1, r2, r3);
                vb[2*dp][0] = r0; vb[2*dp][1] = r1;
                vb[2*dp+1][0] = r2; vb[2*dp+1][1] = r3;
            }
            #pragma unroll
            for (int ni = 0; ni < 8; ni++) mma16816(O[ni], pha[t], vb[ni]);
        }
        __syncthreads();
    }

    // ---- epilogue: write split bf16 y directly ----
    float inv0 = 1.f / l0, inv1 = 1.f / l1;
    size_t ybase = (size_t)(b * SEQ_T + qbase + wi * 16) * D_MODEL + h * 64;
    const int gr = lid >> 2, gc = 2 * (lid & 3);
    #pragma unroll
    for (int ni = 0; ni < 8; ni++) {
        uint32_t hh, ll;
        split2(O[ni][0] * inv0, O[ni][1] * inv0, hh, ll);
        size_t o0 = ybase + (size_t)gr * D_MODEL + ni * 8 + gc;
        *(uint32_t*)(yh + o0) = hh;
        *(uint32_t*)(yl + o0) = ll;
        split2(O[ni][2] * inv1, O[ni][3] * inv1, hh, ll);
        size_t o1 = ybase + (size_t)(gr + 8) * D_MODEL + ni * 8 + gc;
        *(uint32_t*)(yh + o1) = hh;
        *(uint32_t*)(yl + o1) = ll;
    }
}

// ===================== launch ===============================================
extern "C" void kernel_launch(void* const* d_in, const int* in_sizes, int n_in,
                              void* d_out, int out_size)
{
    const float* x   = (const float*)d_in[0];
    // d_in[1] = mask (causal, static — ignored)
    const float* Wq  = (const float*)d_in[2];
    const float* bq  = (const float*)d_in[3];
    const float* Wkv = (const float*)d_in[4];
    const float* bkv = (const float*)d_in[5];
    const float* Wk  = (const float*)d_in[6];
    const float* bk  = (const float*)d_in[7];
    const float* Wv  = (const float*)d_in[8];
    const float* bv  = (const float*)d_in[9];
    const float* Wo  = (const float*)d_in[10];
    const float* bo  = (const float*)d_in[11];
    const float* Wkr = (const float*)d_in[12];
    float* out = (float*)d_out;

    float *q, *k;
    cudaGetSymbolAddress((void**)&q,  g_q);
    cudaGetSymbolAddress((void**)&k,  g_k);
    __nv_bfloat16 *xh, *xl, *kvh, *kvl, *yh, *yl;
    __nv_bfloat16 *qh, *ql, *kh2, *kl2, *vh2, *vl2;
    __nv_bfloat16 *Wqh, *Wql, *Wkvh, *Wkvl, *Wkh, *Wkl, *Wvh, *Wvl, *Woh, *Wol;
    cudaGetSymbolAddress((void**)&xh,  g_xh);   cudaGetSymbolAddress((void**)&xl,  g_xl);
    cudaGetSymbolAddress((void**)&kvh, g_kvh);  cudaGetSymbolAddress((void**)&kvl, g_kvl);
    cudaGetSymbolAddress((void**)&yh,  g_yh);   cudaGetSymbolAddress((void**)&yl,  g_yl);
    cudaGetSymbolAddress((void**)&qh,  g_qh);   cudaGetSymbolAddress((void**)&ql,  g_ql);
    cudaGetSymbolAddress((void**)&kh2, g_kh2);  cudaGetSymbolAddress((void**)&kl2, g_kl2);
    cudaGetSymbolAddress((void**)&vh2, g_vh2);  cudaGetSymbolAddress((void**)&vl2, g_vl2);
    cudaGetSymbolAddress((void**)&Wqh, g_Wqh);  cudaGetSymbolAddress((void**)&Wql, g_Wql);
    cudaGetSymbolAddress((void**)&Wkvh,g_Wkvh); cudaGetSymbolAddress((void**)&Wkvl,g_Wkvl);
    cudaGetSymbolAddress((void**)&Wkh, g_Wkh);  cudaGetSymbolAddress((void**)&Wkl, g_Wkl);
    cudaGetSymbolAddress((void**)&Wvh, g_Wvh);  cudaGetSymbolAddress((void**)&Wvl, g_Wvl);
    cudaGetSymbolAddress((void**)&Woh, g_Woh);  cudaGetSymbolAddress((void**)&Wol, g_Wol);

    cudaFuncSetAttribute(gemm_mma, cudaFuncAttributeMaxDynamicSharedMemorySize, GEMM_SMEM);
    cudaFuncSetAttribute(flash_attn_mma, cudaFuncAttributeMaxDynamicSharedMemorySize, FA_SMEM);

    // weight transpose+split
    wsplit_t<<<dim3(D_MODEL/32, D_MODEL/32), 256>>>(Wq,  Wqh,  Wql,  D_MODEL, D_MODEL);
    wsplit_t<<<dim3(KV_DIM/32,  D_MODEL/32), 256>>>(Wkv, Wkvh, Wkvl, D_MODEL, KV_DIM);
    wsplit_t<<<dim3(D_MODEL/32, KV_DIM/32),  256>>>(Wk,  Wkh,  Wkl,  KV_DIM,  D_MODEL);
    wsplit_t<<<dim3(D_MODEL/32, KV_DIM/32),  256>>>(Wv,  Wvh,  Wvl,  KV_DIM,  D_MODEL);
    wsplit_t<<<dim3(D_MODEL/32, D_MODEL/32), 256>>>(Wo,  Woh,  Wol,  D_MODEL, D_MODEL);
    fsplit4<<<(ROWS * D_MODEL / 4 + 255) / 256, 256>>>(x, xh, xl, ROWS * D_MODEL / 4);

    // projections (split outputs fused where the fp32 tensor isn't needed)
    gemm_mma<<<dim3(KV_DIM/128, ROWS/128), 256, GEMM_SMEM>>>(
        xh, xl, Wkvh, Wkvl, bkv, nullptr, kvh, kvl, D_MODEL, KV_DIM);
    gemm_mma<<<dim3(D_MODEL/128, ROWS/128), 256, GEMM_SMEM>>>(
        xh, xl, Wqh, Wql, bq, q, nullptr, nullptr, D_MODEL, D_MODEL);
    gemm_mma<<<dim3(D_MODEL/128, ROWS/128), 256, GEMM_SMEM>>>(
        kvh, kvl, Wkh, Wkl, bk, k, nullptr, nullptr, KV_DIM, D_MODEL);
    gemm_mma<<<dim3(D_MODEL/128, ROWS/128), 256, GEMM_SMEM>>>(
        kvh, kvl, Wvh, Wvl, bv, nullptr, vh2, vl2, KV_DIM, D_MODEL);

    // position transforms (emit split bf16 directly)
    rope_q_split<<<(ROWS * N_HEADS * 32) / 256, 256>>>(q, qh, ql);
    k_transform_split<<<(ROWS * N_HEADS) / KT_PAIRS, 256>>>(k, Wkr, kh2, kl2);

    // attention (tensor path, cp.async pipelined) -> split y
    flash_attn_mma<<<dim3(SEQ_T / 64, N_HEADS, BATCH), 128, FA_SMEM>>>(
        qh, ql, kh2, kl2, vh2, vl2, yh, yl);

    // output projection
    gemm_mma<<<dim3(D_MODEL/128, ROWS/128), 256, GEMM_SMEM>>>(
        yh, yl, Woh, Wol, bo, out, nullptr, nullptr, D_MODEL, D_MODEL);
}